// round 1
// baseline (speedup 1.0000x reference)
#include <cuda_runtime.h>

// Problem constants
// B=8, N=1024, C=768, H=12, HD=64, R=16
#define NTOK   8192          // B*N
#define CDIM   768
#define QKVCOL 2304          // 3*C
#define BHDIM  96            // B*H
#define SEQ    1024
#define HDIM   64
#define SCALE_F 0.125f       // HD^-0.5

// Scratch (device globals; no allocation allowed)
__device__ float g_weff[3 * 768 * 768];            // effective W for q,k,v
__device__ float g_qkv [3 * 96 * 1024 * 64];       // [m][b*h][n][d]
__device__ float g_att [96 * 1024 * 64];           // attention output, head layout

// ---------------------------------------------------------------------------
// Kernel 1: fold LoRA into effective weights: Weff = W + bw * (la @ lb)
// ---------------------------------------------------------------------------
__global__ void build_weff(const float* __restrict__ Wq, const float* __restrict__ Wk,
                           const float* __restrict__ Wv,
                           const float* __restrict__ laq, const float* __restrict__ lbq,
                           const float* __restrict__ lak, const float* __restrict__ lbk,
                           const float* __restrict__ lav, const float* __restrict__ lbv,
                           const float* __restrict__ bw) {
    int idx = blockIdx.x * blockDim.x + threadIdx.x;
    if (idx >= 3 * 768 * 768) return;
    int m  = idx / (768 * 768);
    int rc = idx - m * (768 * 768);
    int k  = rc / 768;
    int c  = rc - k * 768;
    const float* W  = (m == 0) ? Wq  : (m == 1 ? Wk  : Wv);
    const float* la = (m == 0) ? laq : (m == 1 ? lak : lav);
    const float* lb = (m == 0) ? lbq : (m == 1 ? lbk : lbv);
    float s = 0.f;
#pragma unroll
    for (int r = 0; r < 16; r++)
        s += la[k * 16 + r] * lb[r * 768 + c];
    g_weff[idx] = W[rc] + bw[m] * s;
}

// ---------------------------------------------------------------------------
// Kernel 2: QKV = X @ Weff   (M=8192, N=2304, K=768), output in head layout
// 64x64 tile, BK=16, 256 threads, 4x4 register block per thread
// ---------------------------------------------------------------------------
__global__ __launch_bounds__(256) void gemm_qkv(const float* __restrict__ X) {
    __shared__ float As[16][65];
    __shared__ float Bs[16][64];

    int tid = threadIdx.x;
    int tx = tid & 15, ty = tid >> 4;
    int r0 = ty * 4, c0 = tx * 4;
    int rowBase = blockIdx.y * 64;
    int colBase = blockIdx.x * 64;
    int m   = colBase / 768;
    int cc0 = colBase - m * 768;
    const float* Wm = g_weff + (size_t)m * 768 * 768;

    int la_r = (tid * 4) >> 4;   // A: this thread's row
    int la_k = (tid * 4) & 15;   // A: starting kk (4 consecutive)
    int lb_k = (tid * 4) >> 6;   // B: kk row
    int lb_c = (tid * 4) & 63;   // B: starting col (4 consecutive)

    float acc[4][4] = {};

    for (int k0 = 0; k0 < 768; k0 += 16) {
        float4 av = *(const float4*)(X  + (size_t)(rowBase + la_r) * 768 + k0 + la_k);
        float4 bv = *(const float4*)(Wm + (size_t)(k0 + lb_k) * 768 + cc0 + lb_c);
        __syncthreads();
        As[la_k + 0][la_r] = av.x;
        As[la_k + 1][la_r] = av.y;
        As[la_k + 2][la_r] = av.z;
        As[la_k + 3][la_r] = av.w;
        *(float4*)&Bs[lb_k][lb_c] = bv;
        __syncthreads();
#pragma unroll
        for (int kk = 0; kk < 16; kk++) {
            float a[4], b[4];
#pragma unroll
            for (int i = 0; i < 4; i++) a[i] = As[kk][r0 + i];
#pragma unroll
            for (int j = 0; j < 4; j++) b[j] = Bs[kk][c0 + j];
#pragma unroll
            for (int i = 0; i < 4; i++)
#pragma unroll
                for (int j = 0; j < 4; j++)
                    acc[i][j] += a[i] * b[j];
        }
    }

    // epilogue: write into [m][b*12+h][n][d]
    int h = cc0 >> 6;     // 64-col tile always within one head
#pragma unroll
    for (int i = 0; i < 4; i++) {
        int row = rowBase + r0 + i;
        int b_ = row >> 10, n = row & 1023;
        float* dst = g_qkv + (size_t)((m * 8 + b_) * 12 + h) * 65536 + n * 64 + c0;
        float4 v = make_float4(acc[i][0], acc[i][1], acc[i][2], acc[i][3]);
        *(float4*)dst = v;
    }
}

// ---------------------------------------------------------------------------
// Kernel 3: flash attention (fp32 online softmax)
// grid: (N/64, B*H); block 256 threads. BM=64 query rows, BN=32 key rows.
// ---------------------------------------------------------------------------
__global__ __launch_bounds__(256) void flash_attn() {
    __shared__ float Qs [64 * 64];   // [r][d]
    __shared__ float KsT[64 * 33];   // [d][col]  (transposed K tile)
    __shared__ float Vs [32 * 65];   // [kk][d]
    __shared__ float Ps [64 * 33];   // [r][kk]

    int tid = threadIdx.x;
    int tx = tid & 15, ty = tid >> 4;
    int r0 = ty * 4;
    int cs0 = tx * 2;    // S-tile col base (BN=32)
    int c0  = tx * 4;    // O-tile col base (HD=64)

    int bh = blockIdx.y;
    int qt = blockIdx.x;
    const float* Qg = g_qkv + (size_t)bh * 65536 + qt * 4096;
    const float* Kg = g_qkv + 6291456  + (size_t)bh * 65536;
    const float* Vg = g_qkv + 12582912 + (size_t)bh * 65536;

    // load Q tile (64x64)
#pragma unroll
    for (int l = 0; l < 16; l++)
        Qs[tid + l * 256] = Qg[tid + l * 256];

    float mi[4], li[4], acc[4][4];
#pragma unroll
    for (int i = 0; i < 4; i++) {
        mi[i] = -3.0e38f; li[i] = 0.f;
#pragma unroll
        for (int j = 0; j < 4; j++) acc[i][j] = 0.f;
    }

    for (int t = 0; t < 32; t++) {
        __syncthreads();   // protect KsT/Vs/Ps from previous iteration readers
#pragma unroll
        for (int l = 0; l < 8; l++) {
            int idx = tid + l * 256;          // 0..2047
            int rr = idx >> 6, dd = idx & 63;
            KsT[dd * 33 + rr] = Kg[t * 2048 + idx];
            Vs [rr * 65 + dd] = Vg[t * 2048 + idx];
        }
        __syncthreads();

        // S = (Q @ K^T) * scale, tile 64x32, each thread 4x2
        float s[4][2] = {};
#pragma unroll
        for (int kk = 0; kk < 64; kk++) {
            float q[4];
#pragma unroll
            for (int i = 0; i < 4; i++) q[i] = Qs[(r0 + i) * 64 + kk];
            float k0v = KsT[kk * 33 + cs0];
            float k1v = KsT[kk * 33 + cs0 + 1];
#pragma unroll
            for (int i = 0; i < 4; i++) {
                s[i][0] += q[i] * k0v;
                s[i][1] += q[i] * k1v;
            }
        }

        // online softmax update per row
#pragma unroll
        for (int i = 0; i < 4; i++) {
            s[i][0] *= SCALE_F; s[i][1] *= SCALE_F;
            float tm = fmaxf(s[i][0], s[i][1]);
            tm = fmaxf(tm, __shfl_xor_sync(0xffffffffu, tm, 8));
            tm = fmaxf(tm, __shfl_xor_sync(0xffffffffu, tm, 4));
            tm = fmaxf(tm, __shfl_xor_sync(0xffffffffu, tm, 2));
            tm = fmaxf(tm, __shfl_xor_sync(0xffffffffu, tm, 1));
            float mnew = fmaxf(mi[i], tm);
            float alpha = __expf(mi[i] - mnew);
            float p0 = __expf(s[i][0] - mnew);
            float p1 = __expf(s[i][1] - mnew);
            float rs = p0 + p1;
            rs += __shfl_xor_sync(0xffffffffu, rs, 8);
            rs += __shfl_xor_sync(0xffffffffu, rs, 4);
            rs += __shfl_xor_sync(0xffffffffu, rs, 2);
            rs += __shfl_xor_sync(0xffffffffu, rs, 1);
            li[i] = li[i] * alpha + rs;
            mi[i] = mnew;
#pragma unroll
            for (int j = 0; j < 4; j++) acc[i][j] *= alpha;
            Ps[(r0 + i) * 33 + cs0]     = p0;
            Ps[(r0 + i) * 33 + cs0 + 1] = p1;
        }
        __syncthreads();

        // O += P @ V  (P: 64x32, V: 32x64), each thread 4x4
#pragma unroll
        for (int kk = 0; kk < 32; kk++) {
            float p[4], v[4];
#pragma unroll
            for (int i = 0; i < 4; i++) p[i] = Ps[(r0 + i) * 33 + kk];
#pragma unroll
            for (int j = 0; j < 4; j++) v[j] = Vs[kk * 65 + c0 + j];
#pragma unroll
            for (int i = 0; i < 4; i++)
#pragma unroll
                for (int j = 0; j < 4; j++)
                    acc[i][j] += p[i] * v[j];
        }
    }

    // normalize and write out (head layout)
#pragma unroll
    for (int i = 0; i < 4; i++) {
        float inv = 1.f / li[i];
        float* dst = g_att + (size_t)bh * 65536 + (qt * 64 + r0 + i) * 64 + c0;
        float4 v = make_float4(acc[i][0] * inv, acc[i][1] * inv,
                               acc[i][2] * inv, acc[i][3] * inv);
        *(float4*)dst = v;
    }
}

// ---------------------------------------------------------------------------
// Kernel 4: OUT = gather(g_att) @ Wp + bp   (M=8192, N=768, K=768)
// ---------------------------------------------------------------------------
__global__ __launch_bounds__(256) void gemm_out(const float* __restrict__ Wp,
                                                const float* __restrict__ bp,
                                                float* __restrict__ out) {
    __shared__ float As[16][65];
    __shared__ float Bs[16][64];

    int tid = threadIdx.x;
    int tx = tid & 15, ty = tid >> 4;
    int r0 = ty * 4, c0 = tx * 4;
    int rowBase = blockIdx.y * 64;
    int colBase = blockIdx.x * 64;

    int la_r = (tid * 4) >> 4;
    int la_k = (tid * 4) & 15;
    int lb_k = (tid * 4) >> 6;
    int lb_c = (tid * 4) & 63;

    int rowA = rowBase + la_r;
    int bA = rowA >> 10, nA = rowA & 1023;

    float acc[4][4] = {};

    for (int k0 = 0; k0 < 768; k0 += 16) {
        int k = k0 + la_k;   // 4 consecutive k within one 64-block (k0 mult of 16)
        const float* srcA = g_att + (size_t)(bA * 12 + (k >> 6)) * 65536 + nA * 64 + (k & 63);
        float4 av = *(const float4*)srcA;
        float4 bv = *(const float4*)(Wp + (size_t)(k0 + lb_k) * 768 + colBase + lb_c);
        __syncthreads();
        As[la_k + 0][la_r] = av.x;
        As[la_k + 1][la_r] = av.y;
        As[la_k + 2][la_r] = av.z;
        As[la_k + 3][la_r] = av.w;
        *(float4*)&Bs[lb_k][lb_c] = bv;
        __syncthreads();
#pragma unroll
        for (int kk = 0; kk < 16; kk++) {
            float a[4], b[4];
#pragma unroll
            for (int i = 0; i < 4; i++) a[i] = As[kk][r0 + i];
#pragma unroll
            for (int j = 0; j < 4; j++) b[j] = Bs[kk][c0 + j];
#pragma unroll
            for (int i = 0; i < 4; i++)
#pragma unroll
                for (int j = 0; j < 4; j++)
                    acc[i][j] += a[i] * b[j];
        }
    }

    float bias[4];
#pragma unroll
    for (int j = 0; j < 4; j++) bias[j] = bp[colBase + c0 + j];
#pragma unroll
    for (int i = 0; i < 4; i++) {
        int row = rowBase + r0 + i;
        float* dst = out + (size_t)row * 768 + colBase + c0;
        float4 v = make_float4(acc[i][0] + bias[0], acc[i][1] + bias[1],
                               acc[i][2] + bias[2], acc[i][3] + bias[3]);
        *(float4*)dst = v;
    }
}

// ---------------------------------------------------------------------------
// Launch
// ---------------------------------------------------------------------------
extern "C" void kernel_launch(void* const* d_in, const int* in_sizes, int n_in,
                              void* d_out, int out_size) {
    const float* x   = (const float*)d_in[0];
    const float* Wq  = (const float*)d_in[1];
    const float* Wk  = (const float*)d_in[2];
    const float* Wv  = (const float*)d_in[3];
    const float* Wp  = (const float*)d_in[4];
    const float* bp  = (const float*)d_in[5];
    const float* laq = (const float*)d_in[6];
    const float* lbq = (const float*)d_in[7];
    const float* lak = (const float*)d_in[8];
    const float* lbk = (const float*)d_in[9];
    const float* lav = (const float*)d_in[10];
    const float* lbv = (const float*)d_in[11];
    const float* bw  = (const float*)d_in[12];
    float* out = (float*)d_out;

    build_weff<<<(3 * 768 * 768 + 255) / 256, 256>>>(Wq, Wk, Wv, laq, lbq, lak, lbk,
                                                     lav, lbv, bw);
    gemm_qkv<<<dim3(QKVCOL / 64, NTOK / 64), 256>>>(x);
    flash_attn<<<dim3(SEQ / 64, BHDIM), 256>>>();
    gemm_out<<<dim3(CDIM / 64, NTOK / 64), 256>>>(Wp, bp, out);
}

// round 6
// speedup vs baseline: 1.5266x; 1.5266x over previous
#include <cuda_runtime.h>
#include <cstdint>

// Problem constants: B=8, N=1024, C=768, H=12, HD=64, R=16
#define NTOK   8192
#define CDIM   768
#define QKVCOL 2304
#define BHDIM  96
#define SEQ    1024
#define SCALE_F 0.125f

// ---------------------------------------------------------------------------
// Device scratch (no allocation allowed)
// ---------------------------------------------------------------------------
__device__ float g_weffT[3 * 768 * 768];     // effective W, TRANSPOSED: [m][out_c][in_k]
__device__ float g_wpT  [768 * 768];         // Wp transposed: [out_c][in_k]
__device__ float g_qkv  [3 * 96 * 1024 * 64];// [m][b*12+h][n][d]
__device__ float g_att  [96 * 1024 * 64];    // attention out, head layout

// ---------------------------------------------------------------------------
// Helpers (all base-sm_103 legal: ldmatrix sm_75+, mma.sync tf32 sm_80+)
// ---------------------------------------------------------------------------
__device__ __forceinline__ uint32_t smem_u32(const void* p) {
    uint32_t a;
    asm("{ .reg .u64 t; cvta.to.shared.u64 t, %1; cvt.u32.u64 %0, t; }" : "=r"(a) : "l"(p));
    return a;
}
__device__ __forceinline__ float to_tf32(float x) {
    float r;
    asm("cvt.rna.tf32.f32 %0, %1;" : "=f"(r) : "f"(x));
    return r;
}
// SW128 swizzle (Swizzle<3,4,3>): XOR byte-addr bits [4:7) with bits [7:10)
__device__ __forceinline__ uint32_t sw128(uint32_t off) {
    return off ^ ((off >> 3) & 0x70);
}

#define LDMX4(r, addr)                                                            \
    asm volatile("ldmatrix.sync.aligned.m8n8.x4.shared.b16 {%0,%1,%2,%3}, [%4];"  \
        : "=r"((r)[0]), "=r"((r)[1]), "=r"((r)[2]), "=r"((r)[3]) : "r"(addr))

#define MMA_TF32(c, a, b0, b1)                                                    \
    asm volatile("mma.sync.aligned.m16n8k8.row.col.f32.tf32.tf32.f32 "            \
        "{%0,%1,%2,%3}, {%4,%5,%6,%7}, {%8,%9}, {%0,%1,%2,%3};"                   \
        : "+f"((c)[0]), "+f"((c)[1]), "+f"((c)[2]), "+f"((c)[3])                  \
        : "r"((a)[0]), "r"((a)[1]), "r"((a)[2]), "r"((a)[3]), "r"(b0), "r"(b1))

// ---------------------------------------------------------------------------
// Kernel 1: WeffT[m][c][k] = W[k][c] + bw[m] * (la @ lb)[k][c]   (transposed)
// grid (24, 24, 3), block 256
// ---------------------------------------------------------------------------
__global__ __launch_bounds__(256) void build_weffT(
    const float* __restrict__ Wq, const float* __restrict__ Wk, const float* __restrict__ Wv,
    const float* __restrict__ laq, const float* __restrict__ lbq,
    const float* __restrict__ lak, const float* __restrict__ lbk,
    const float* __restrict__ lav, const float* __restrict__ lbv,
    const float* __restrict__ bw) {
    __shared__ float Wt[32][33];   // [k][c]
    __shared__ float las[32][16];  // [k][r]
    __shared__ float lbs[16][33];  // [r][c]

    int mat = blockIdx.z;
    const float* W  = (mat == 0) ? Wq  : (mat == 1 ? Wk  : Wv);
    const float* la = (mat == 0) ? laq : (mat == 1 ? lak : lav);
    const float* lb = (mat == 0) ? lbq : (mat == 1 ? lbk : lbv);
    int k0 = blockIdx.x * 32, c0 = blockIdx.y * 32;
    int tid = threadIdx.x, tx = tid & 31, ty = tid >> 5;

#pragma unroll
    for (int i = 0; i < 4; i++) {
        int kk = ty + i * 8;
        Wt[kk][tx] = W[(k0 + kk) * 768 + c0 + tx];
    }
#pragma unroll
    for (int e = tid; e < 512; e += 256)
        las[e >> 4][e & 15] = la[(k0 + (e >> 4)) * 16 + (e & 15)];
#pragma unroll
    for (int e = tid; e < 512; e += 256)
        lbs[e >> 5][e & 31] = lb[(e >> 5) * 768 + c0 + (e & 31)];
    __syncthreads();

    float w = bw[mat];
#pragma unroll
    for (int i = 0; i < 4; i++) {
        int c = ty + i * 8;
        float s = 0.f;
#pragma unroll
        for (int r = 0; r < 16; r++) s += las[tx][r] * lbs[r][c];
        g_weffT[(size_t)mat * 589824 + (size_t)(c0 + c) * 768 + k0 + tx] = Wt[tx][c] + w * s;
    }
}

// ---------------------------------------------------------------------------
// Kernel 2: WpT[c][k] = Wp[k][c].  grid (24,24), block 256
// ---------------------------------------------------------------------------
__global__ __launch_bounds__(256) void transpose_wp(const float* __restrict__ Wp) {
    __shared__ float Wt[32][33];
    int k0 = blockIdx.x * 32, c0 = blockIdx.y * 32;
    int tid = threadIdx.x, tx = tid & 31, ty = tid >> 5;
#pragma unroll
    for (int i = 0; i < 4; i++) {
        int kk = ty + i * 8;
        Wt[kk][tx] = Wp[(k0 + kk) * 768 + c0 + tx];
    }
    __syncthreads();
#pragma unroll
    for (int i = 0; i < 4; i++) {
        int c = ty + i * 8;
        g_wpT[(size_t)(c0 + c) * 768 + k0 + tx] = Wt[tx][c];
    }
}

// ---------------------------------------------------------------------------
// Kernel 3: QKV = X @ Weff via mma.sync tf32.  CTA tile 128x128, BK=32.
// grid (18, 64), block 256 (8 warps = 4(m) x 2(n); warp tile 32x64)
// ---------------------------------------------------------------------------
__global__ __launch_bounds__(256) void gemm_qkv_mma(const float* __restrict__ X) {
    __shared__ __align__(128) float sA[128 * 32];   // [m][k] SW128 rows of 128B
    __shared__ __align__(128) float sB[128 * 32];   // [n][k] SW128

    int tid = threadIdx.x;
    int warp = tid >> 5, lane = tid & 31;
    int warpM = warp >> 1, warpN = warp & 1;
    int rowBase = blockIdx.y * 128;
    int colBase = blockIdx.x * 128;
    int mat = colBase / 768;
    int cc  = colBase - mat * 768;
    const float* Bsrc = g_weffT + (size_t)mat * 589824 + (size_t)cc * 768;

    uint32_t aBase = smem_u32(sA), bBase = smem_u32(sB);
    int lr = lane & 7, blk = lane >> 3;
    // A fragment blocks: [r0k0, r8k0, r0k4, r8k4]
    uint32_t aOff = (uint32_t)((warpM * 32 + (blk & 1) * 8 + lr) * 128 + (blk >> 1) * 16);
    // B fragment blocks: [n0k0, n0k4, n8k0, n8k4] (2 n-tiles per ldmatrix.x4)
    uint32_t bOff = (uint32_t)((warpN * 64 + (blk >> 1) * 8 + lr) * 128 + (blk & 1) * 16);

    float acc[2][8][4];
#pragma unroll
    for (int mt = 0; mt < 2; mt++)
#pragma unroll
        for (int nt = 0; nt < 8; nt++)
#pragma unroll
            for (int q = 0; q < 4; q++) acc[mt][nt][q] = 0.f;

    for (int it = 0; it < 24; it++) {
        int k0 = it * 32;
        float4 va[4], vb[4];
#pragma unroll
        for (int l = 0; l < 4; l++) {
            int idx = tid + l * 256;
            int row = idx >> 3, ci = idx & 7;
            va[l] = *(const float4*)(X    + (size_t)(rowBase + row) * 768 + k0 + ci * 4);
            vb[l] = *(const float4*)(Bsrc + (size_t)row * 768 + k0 + ci * 4);
        }
        __syncthreads();
#pragma unroll
        for (int l = 0; l < 4; l++) {
            int idx = tid + l * 256;
            int row = idx >> 3, ci = idx & 7;
            uint32_t sw = sw128((uint32_t)(row * 128 + ci * 16));
            float4 ta = make_float4(to_tf32(va[l].x), to_tf32(va[l].y),
                                    to_tf32(va[l].z), to_tf32(va[l].w));
            float4 tb = make_float4(to_tf32(vb[l].x), to_tf32(vb[l].y),
                                    to_tf32(vb[l].z), to_tf32(vb[l].w));
            *(float4*)((char*)sA + sw) = ta;
            *(float4*)((char*)sB + sw) = tb;
        }
        __syncthreads();

#pragma unroll
        for (int ks = 0; ks < 4; ks++) {
            uint32_t af[2][4], bf[4][4];
#pragma unroll
            for (int mt = 0; mt < 2; mt++)
                LDMX4(af[mt], aBase + sw128(aOff + mt * 2048 + ks * 32));
#pragma unroll
            for (int np = 0; np < 4; np++)
                LDMX4(bf[np], bBase + sw128(bOff + np * 2048 + ks * 32));
#pragma unroll
            for (int mt = 0; mt < 2; mt++)
#pragma unroll
                for (int np = 0; np < 4; np++) {
                    MMA_TF32(acc[mt][np * 2],     af[mt], bf[np][0], bf[np][1]);
                    MMA_TF32(acc[mt][np * 2 + 1], af[mt], bf[np][2], bf[np][3]);
                }
        }
        __syncthreads();
    }

    // epilogue: write into [m][b*12+h][n][d]
    int h = cc / 64 + warpN;
#pragma unroll
    for (int mt = 0; mt < 2; mt++) {
        int r0g = rowBase + warpM * 32 + mt * 16 + (lane >> 2);
        int b_ = r0g >> 10, n = r0g & 1023;
        float* dstBase = g_qkv + (size_t)((mat * 8 + b_) * 12 + h) * 65536;
#pragma unroll
        for (int nt = 0; nt < 8; nt++) {
            int d = nt * 8 + 2 * (lane & 3);
            *(float2*)(dstBase + n * 64 + d)       = make_float2(acc[mt][nt][0], acc[mt][nt][1]);
            *(float2*)(dstBase + (n + 8) * 64 + d) = make_float2(acc[mt][nt][2], acc[mt][nt][3]);
        }
    }
}

// ---------------------------------------------------------------------------
// Kernel 4: flash attention (fp32 online softmax) — unchanged (R1-verified)
// grid: (N/64, B*H); block 256
// ---------------------------------------------------------------------------
__global__ __launch_bounds__(256) void flash_attn() {
    __shared__ float Qs [64 * 64];
    __shared__ float KsT[64 * 33];
    __shared__ float Vs [32 * 65];
    __shared__ float Ps [64 * 33];

    int tid = threadIdx.x;
    int tx = tid & 15, ty = tid >> 4;
    int r0 = ty * 4;
    int cs0 = tx * 2;
    int c0  = tx * 4;

    int bh = blockIdx.y;
    int qt = blockIdx.x;
    const float* Qg = g_qkv + (size_t)bh * 65536 + qt * 4096;
    const float* Kg = g_qkv + 6291456  + (size_t)bh * 65536;
    const float* Vg = g_qkv + 12582912 + (size_t)bh * 65536;

#pragma unroll
    for (int l = 0; l < 16; l++)
        Qs[tid + l * 256] = Qg[tid + l * 256];

    float mi[4], li[4], acc[4][4];
#pragma unroll
    for (int i = 0; i < 4; i++) {
        mi[i] = -3.0e38f; li[i] = 0.f;
#pragma unroll
        for (int j = 0; j < 4; j++) acc[i][j] = 0.f;
    }

    for (int t = 0; t < 32; t++) {
        __syncthreads();
#pragma unroll
        for (int l = 0; l < 8; l++) {
            int idx = tid + l * 256;
            int rr = idx >> 6, dd = idx & 63;
            KsT[dd * 33 + rr] = Kg[t * 2048 + idx];
            Vs [rr * 65 + dd] = Vg[t * 2048 + idx];
        }
        __syncthreads();

        float s[4][2] = {};
#pragma unroll
        for (int kk = 0; kk < 64; kk++) {
            float q[4];
#pragma unroll
            for (int i = 0; i < 4; i++) q[i] = Qs[(r0 + i) * 64 + kk];
            float k0v = KsT[kk * 33 + cs0];
            float k1v = KsT[kk * 33 + cs0 + 1];
#pragma unroll
            for (int i = 0; i < 4; i++) {
                s[i][0] += q[i] * k0v;
                s[i][1] += q[i] * k1v;
            }
        }

#pragma unroll
        for (int i = 0; i < 4; i++) {
            s[i][0] *= SCALE_F; s[i][1] *= SCALE_F;
            float tm = fmaxf(s[i][0], s[i][1]);
            tm = fmaxf(tm, __shfl_xor_sync(0xffffffffu, tm, 8));
            tm = fmaxf(tm, __shfl_xor_sync(0xffffffffu, tm, 4));
            tm = fmaxf(tm, __shfl_xor_sync(0xffffffffu, tm, 2));
            tm = fmaxf(tm, __shfl_xor_sync(0xffffffffu, tm, 1));
            float mnew = fmaxf(mi[i], tm);
            float alpha = __expf(mi[i] - mnew);
            float p0 = __expf(s[i][0] - mnew);
            float p1 = __expf(s[i][1] - mnew);
            float rs = p0 + p1;
            rs += __shfl_xor_sync(0xffffffffu, rs, 8);
            rs += __shfl_xor_sync(0xffffffffu, rs, 4);
            rs += __shfl_xor_sync(0xffffffffu, rs, 2);
            rs += __shfl_xor_sync(0xffffffffu, rs, 1);
            li[i] = li[i] * alpha + rs;
            mi[i] = mnew;
#pragma unroll
            for (int j = 0; j < 4; j++) acc[i][j] *= alpha;
            Ps[(r0 + i) * 33 + cs0]     = p0;
            Ps[(r0 + i) * 33 + cs0 + 1] = p1;
        }
        __syncthreads();

#pragma unroll
        for (int kk = 0; kk < 32; kk++) {
            float p[4], v[4];
#pragma unroll
            for (int i = 0; i < 4; i++) p[i] = Ps[(r0 + i) * 33 + kk];
#pragma unroll
            for (int j = 0; j < 4; j++) v[j] = Vs[kk * 65 + c0 + j];
#pragma unroll
            for (int i = 0; i < 4; i++)
#pragma unroll
                for (int j = 0; j < 4; j++)
                    acc[i][j] += p[i] * v[j];
        }
    }

#pragma unroll
    for (int i = 0; i < 4; i++) {
        float inv = 1.f / li[i];
        float* dst = g_att + (size_t)bh * 65536 + (qt * 64 + r0 + i) * 64 + c0;
        float4 v = make_float4(acc[i][0] * inv, acc[i][1] * inv,
                               acc[i][2] * inv, acc[i][3] * inv);
        *(float4*)dst = v;
    }
}

// ---------------------------------------------------------------------------
// Kernel 5: OUT = gather(g_att) @ Wp + bp  via mma.sync tf32
// grid (6, 64), block 256
// ---------------------------------------------------------------------------
__global__ __launch_bounds__(256) void gemm_out_mma(const float* __restrict__ bp,
                                                    float* __restrict__ out) {
    __shared__ __align__(128) float sA[128 * 32];
    __shared__ __align__(128) float sB[128 * 32];

    int tid = threadIdx.x;
    int warp = tid >> 5, lane = tid & 31;
    int warpM = warp >> 1, warpN = warp & 1;
    int rowBase = blockIdx.y * 128;
    int colBase = blockIdx.x * 128;
    const float* Bsrc = g_wpT + (size_t)colBase * 768;

    uint32_t aBase = smem_u32(sA), bBase = smem_u32(sB);
    int lr = lane & 7, blk = lane >> 3;
    uint32_t aOff = (uint32_t)((warpM * 32 + (blk & 1) * 8 + lr) * 128 + (blk >> 1) * 16);
    uint32_t bOff = (uint32_t)((warpN * 64 + (blk >> 1) * 8 + lr) * 128 + (blk & 1) * 16);

    float acc[2][8][4];
#pragma unroll
    for (int mt = 0; mt < 2; mt++)
#pragma unroll
        for (int nt = 0; nt < 8; nt++)
#pragma unroll
            for (int q = 0; q < 4; q++) acc[mt][nt][q] = 0.f;

    for (int it = 0; it < 24; it++) {
        int k0 = it * 32;
        int h = k0 >> 6, dbase = k0 & 63;
        float4 va[4], vb[4];
#pragma unroll
        for (int l = 0; l < 4; l++) {
            int idx = tid + l * 256;
            int row = idx >> 3, ci = idx & 7;
            int grow = rowBase + row;
            int b_ = grow >> 10, n = grow & 1023;
            va[l] = *(const float4*)(g_att + (size_t)(b_ * 12 + h) * 65536 + n * 64 + dbase + ci * 4);
            vb[l] = *(const float4*)(Bsrc + (size_t)row * 768 + k0 + ci * 4);
        }
        __syncthreads();
#pragma unroll
        for (int l = 0; l < 4; l++) {
            int idx = tid + l * 256;
            int row = idx >> 3, ci = idx & 7;
            uint32_t sw = sw128((uint32_t)(row * 128 + ci * 16));
            float4 ta = make_float4(to_tf32(va[l].x), to_tf32(va[l].y),
                                    to_tf32(va[l].z), to_tf32(va[l].w));
            float4 tb = make_float4(to_tf32(vb[l].x), to_tf32(vb[l].y),
                                    to_tf32(vb[l].z), to_tf32(vb[l].w));
            *(float4*)((char*)sA + sw) = ta;
            *(float4*)((char*)sB + sw) = tb;
        }
        __syncthreads();

#pragma unroll
        for (int ks = 0; ks < 4; ks++) {
            uint32_t af[2][4], bf[4][4];
#pragma unroll
            for (int mt = 0; mt < 2; mt++)
                LDMX4(af[mt], aBase + sw128(aOff + mt * 2048 + ks * 32));
#pragma unroll
            for (int np = 0; np < 4; np++)
                LDMX4(bf[np], bBase + sw128(bOff + np * 2048 + ks * 32));
#pragma unroll
            for (int mt = 0; mt < 2; mt++)
#pragma unroll
                for (int np = 0; np < 4; np++) {
                    MMA_TF32(acc[mt][np * 2],     af[mt], bf[np][0], bf[np][1]);
                    MMA_TF32(acc[mt][np * 2 + 1], af[mt], bf[np][2], bf[np][3]);
                }
        }
        __syncthreads();
    }

#pragma unroll
    for (int mt = 0; mt < 2; mt++) {
        int r0g = rowBase + warpM * 32 + mt * 16 + (lane >> 2);
#pragma unroll
        for (int nt = 0; nt < 8; nt++) {
            int col = colBase + warpN * 64 + nt * 8 + 2 * (lane & 3);
            float2 bb = *(const float2*)(bp + col);
            *(float2*)(out + (size_t)r0g * 768 + col) =
                make_float2(acc[mt][nt][0] + bb.x, acc[mt][nt][1] + bb.y);
            *(float2*)(out + (size_t)(r0g + 8) * 768 + col) =
                make_float2(acc[mt][nt][2] + bb.x, acc[mt][nt][3] + bb.y);
        }
    }
}

// ---------------------------------------------------------------------------
// Launch
// ---------------------------------------------------------------------------
extern "C" void kernel_launch(void* const* d_in, const int* in_sizes, int n_in,
                              void* d_out, int out_size) {
    const float* x   = (const float*)d_in[0];
    const float* Wq  = (const float*)d_in[1];
    const float* Wk  = (const float*)d_in[2];
    const float* Wv  = (const float*)d_in[3];
    const float* Wp  = (const float*)d_in[4];
    const float* bp  = (const float*)d_in[5];
    const float* laq = (const float*)d_in[6];
    const float* lbq = (const float*)d_in[7];
    const float* lak = (const float*)d_in[8];
    const float* lbk = (const float*)d_in[9];
    const float* lav = (const float*)d_in[10];
    const float* lbv = (const float*)d_in[11];
    const float* bw  = (const float*)d_in[12];
    float* out = (float*)d_out;

    build_weffT<<<dim3(24, 24, 3), 256>>>(Wq, Wk, Wv, laq, lbq, lak, lbk, lav, lbv, bw);
    transpose_wp<<<dim3(24, 24), 256>>>(Wp);
    gemm_qkv_mma<<<dim3(18, 64), 256>>>(x);
    flash_attn<<<dim3(SEQ / 64, BHDIM), 256>>>();
    gemm_out_mma<<<dim3(6, 64), 256>>>(bp, out);
}

// round 10
// speedup vs baseline: 2.6355x; 1.7264x over previous
#include <cuda_runtime.h>
#include <cstdint>

// Problem constants: B=8, N=1024, C=768, H=12, HD=64, R=16
#define NTOK   8192
#define CDIM   768
#define QKVCOL 2304
#define BHDIM  96
#define SEQ    1024
#define SCALE_F 0.125f

// ---------------------------------------------------------------------------
// Device scratch (no allocation allowed)
// ---------------------------------------------------------------------------
__device__ float g_weffT[3 * 768 * 768];     // effective W, TRANSPOSED: [m][out_c][in_k]
__device__ float g_wpT  [768 * 768];         // Wp transposed: [out_c][in_k]
__device__ float g_qkv  [3 * 96 * 1024 * 64];// [m][b*12+h][n][d]
__device__ float g_att  [96 * 1024 * 64];    // attention out, head layout

// ---------------------------------------------------------------------------
// Helpers (all base-sm_103 legal: ldmatrix sm_75+, mma.sync tf32 sm_80+)
// ---------------------------------------------------------------------------
__device__ __forceinline__ uint32_t smem_u32(const void* p) {
    uint32_t a;
    asm("{ .reg .u64 t; cvta.to.shared.u64 t, %1; cvt.u32.u64 %0, t; }" : "=r"(a) : "l"(p));
    return a;
}
__device__ __forceinline__ float to_tf32(float x) {
    float r;
    asm("cvt.rna.tf32.f32 %0, %1;" : "=f"(r) : "f"(x));
    return r;
}
// SW128 swizzle (Swizzle<3,4,3>): XOR byte-addr bits [4:7) with bits [7:10)
__device__ __forceinline__ uint32_t sw128(uint32_t off) {
    return off ^ ((off >> 3) & 0x70);
}

#define LDMX4(r, addr)                                                            \
    asm volatile("ldmatrix.sync.aligned.m8n8.x4.shared.b16 {%0,%1,%2,%3}, [%4];"  \
        : "=r"((r)[0]), "=r"((r)[1]), "=r"((r)[2]), "=r"((r)[3]) : "r"(addr))

#define MMA_TF32(c, a, b0, b1)                                                    \
    asm volatile("mma.sync.aligned.m16n8k8.row.col.f32.tf32.tf32.f32 "            \
        "{%0,%1,%2,%3}, {%4,%5,%6,%7}, {%8,%9}, {%0,%1,%2,%3};"                   \
        : "+f"((c)[0]), "+f"((c)[1]), "+f"((c)[2]), "+f"((c)[3])                  \
        : "r"((a)[0]), "r"((a)[1]), "r"((a)[2]), "r"((a)[3]), "r"(b0), "r"(b1))

// ---------------------------------------------------------------------------
// Kernel 1: WeffT[m][c][k] = W[k][c] + bw[m] * (la @ lb)[k][c]   (transposed)
// ---------------------------------------------------------------------------
__global__ __launch_bounds__(256) void build_weffT(
    const float* __restrict__ Wq, const float* __restrict__ Wk, const float* __restrict__ Wv,
    const float* __restrict__ laq, const float* __restrict__ lbq,
    const float* __restrict__ lak, const float* __restrict__ lbk,
    const float* __restrict__ lav, const float* __restrict__ lbv,
    const float* __restrict__ bw) {
    __shared__ float Wt[32][33];
    __shared__ float las[32][16];
    __shared__ float lbs[16][33];

    int mat = blockIdx.z;
    const float* W  = (mat == 0) ? Wq  : (mat == 1 ? Wk  : Wv);
    const float* la = (mat == 0) ? laq : (mat == 1 ? lak : lav);
    const float* lb = (mat == 0) ? lbq : (mat == 1 ? lbk : lbv);
    int k0 = blockIdx.x * 32, c0 = blockIdx.y * 32;
    int tid = threadIdx.x, tx = tid & 31, ty = tid >> 5;

#pragma unroll
    for (int i = 0; i < 4; i++) {
        int kk = ty + i * 8;
        Wt[kk][tx] = W[(k0 + kk) * 768 + c0 + tx];
    }
#pragma unroll
    for (int e = tid; e < 512; e += 256)
        las[e >> 4][e & 15] = la[(k0 + (e >> 4)) * 16 + (e & 15)];
#pragma unroll
    for (int e = tid; e < 512; e += 256)
        lbs[e >> 5][e & 31] = lb[(e >> 5) * 768 + c0 + (e & 31)];
    __syncthreads();

    float w = bw[mat];
#pragma unroll
    for (int i = 0; i < 4; i++) {
        int c = ty + i * 8;
        float s = 0.f;
#pragma unroll
        for (int r = 0; r < 16; r++) s += las[tx][r] * lbs[r][c];
        g_weffT[(size_t)mat * 589824 + (size_t)(c0 + c) * 768 + k0 + tx] = Wt[tx][c] + w * s;
    }
}

// ---------------------------------------------------------------------------
// Kernel 2: WpT[c][k] = Wp[k][c]
// ---------------------------------------------------------------------------
__global__ __launch_bounds__(256) void transpose_wp(const float* __restrict__ Wp) {
    __shared__ float Wt[32][33];
    int k0 = blockIdx.x * 32, c0 = blockIdx.y * 32;
    int tid = threadIdx.x, tx = tid & 31, ty = tid >> 5;
#pragma unroll
    for (int i = 0; i < 4; i++) {
        int kk = ty + i * 8;
        Wt[kk][tx] = Wp[(k0 + kk) * 768 + c0 + tx];
    }
    __syncthreads();
#pragma unroll
    for (int i = 0; i < 4; i++) {
        int c = ty + i * 8;
        g_wpT[(size_t)(c0 + c) * 768 + k0 + tx] = Wt[tx][c];
    }
}

// ---------------------------------------------------------------------------
// Kernel 3: QKV = X @ Weff via mma.sync tf32 (verified R6)
// ---------------------------------------------------------------------------
__global__ __launch_bounds__(256) void gemm_qkv_mma(const float* __restrict__ X) {
    __shared__ __align__(128) float sA[128 * 32];
    __shared__ __align__(128) float sB[128 * 32];

    int tid = threadIdx.x;
    int warp = tid >> 5, lane = tid & 31;
    int warpM = warp >> 1, warpN = warp & 1;
    int rowBase = blockIdx.y * 128;
    int colBase = blockIdx.x * 128;
    int mat = colBase / 768;
    int cc  = colBase - mat * 768;
    const float* Bsrc = g_weffT + (size_t)mat * 589824 + (size_t)cc * 768;

    uint32_t aBase = smem_u32(sA), bBase = smem_u32(sB);
    int lr = lane & 7, blk = lane >> 3;
    uint32_t aOff = (uint32_t)((warpM * 32 + (blk & 1) * 8 + lr) * 128 + (blk >> 1) * 16);
    uint32_t bOff = (uint32_t)((warpN * 64 + (blk >> 1) * 8 + lr) * 128 + (blk & 1) * 16);

    float acc[2][8][4];
#pragma unroll
    for (int mt = 0; mt < 2; mt++)
#pragma unroll
        for (int nt = 0; nt < 8; nt++)
#pragma unroll
            for (int q = 0; q < 4; q++) acc[mt][nt][q] = 0.f;

    for (int it = 0; it < 24; it++) {
        int k0 = it * 32;
        float4 va[4], vb[4];
#pragma unroll
        for (int l = 0; l < 4; l++) {
            int idx = tid + l * 256;
            int row = idx >> 3, ci = idx & 7;
            va[l] = *(const float4*)(X    + (size_t)(rowBase + row) * 768 + k0 + ci * 4);
            vb[l] = *(const float4*)(Bsrc + (size_t)row * 768 + k0 + ci * 4);
        }
        __syncthreads();
#pragma unroll
        for (int l = 0; l < 4; l++) {
            int idx = tid + l * 256;
            int row = idx >> 3, ci = idx & 7;
            uint32_t sw = sw128((uint32_t)(row * 128 + ci * 16));
            *(float4*)((char*)sA + sw) = make_float4(to_tf32(va[l].x), to_tf32(va[l].y),
                                                     to_tf32(va[l].z), to_tf32(va[l].w));
            *(float4*)((char*)sB + sw) = make_float4(to_tf32(vb[l].x), to_tf32(vb[l].y),
                                                     to_tf32(vb[l].z), to_tf32(vb[l].w));
        }
        __syncthreads();

#pragma unroll
        for (int ks = 0; ks < 4; ks++) {
            uint32_t af[2][4], bf[4][4];
#pragma unroll
            for (int mt = 0; mt < 2; mt++)
                LDMX4(af[mt], aBase + sw128(aOff + mt * 2048 + ks * 32));
#pragma unroll
            for (int np = 0; np < 4; np++)
                LDMX4(bf[np], bBase + sw128(bOff + np * 2048 + ks * 32));
#pragma unroll
            for (int mt = 0; mt < 2; mt++)
#pragma unroll
                for (int np = 0; np < 4; np++) {
                    MMA_TF32(acc[mt][np * 2],     af[mt], bf[np][0], bf[np][1]);
                    MMA_TF32(acc[mt][np * 2 + 1], af[mt], bf[np][2], bf[np][3]);
                }
        }
        __syncthreads();
    }

    int h = cc / 64 + warpN;
#pragma unroll
    for (int mt = 0; mt < 2; mt++) {
        int r0g = rowBase + warpM * 32 + mt * 16 + (lane >> 2);
        int b_ = r0g >> 10, n = r0g & 1023;
        float* dstBase = g_qkv + (size_t)((mat * 8 + b_) * 12 + h) * 65536;
#pragma unroll
        for (int nt = 0; nt < 8; nt++) {
            int d = nt * 8 + 2 * (lane & 3);
            *(float2*)(dstBase + n * 64 + d)       = make_float2(acc[mt][nt][0], acc[mt][nt][1]);
            *(float2*)(dstBase + (n + 8) * 64 + d) = make_float2(acc[mt][nt][2], acc[mt][nt][3]);
        }
    }
}

// ---------------------------------------------------------------------------
// Kernel 4: flash attention via mma.sync tf32.
// grid (16, 96), block 128 (4 warps, each m16). BM=64 q rows, BN=32 keys/iter.
// smem panels are 128B rows, SW128 swizzled (conflict-free ldmatrix).
// ---------------------------------------------------------------------------
__global__ __launch_bounds__(128) void flash_mma() {
    __shared__ __align__(128) float Qs[4096];  // 2 panels [64 r][32 d], panel=8KB
    __shared__ __align__(128) float Ks[2048];  // 2 panels [32 n][32 d], panel=4KB
    __shared__ __align__(128) float VT[2048];  // [64 d][32 kk]
    __shared__ __align__(128) float Ps[2048];  // [64 r][32 kk]

    int tid = threadIdx.x;
    int lane = tid & 31;
    int warp = tid >> 5;
    int rw = warp * 16;
    int blk = lane >> 3, lr = lane & 7;
    int bh = blockIdx.y, qt = blockIdx.x;
    const float* Qg = g_qkv + (size_t)bh * 65536 + qt * 4096;
    const float* Kg = g_qkv + 6291456  + (size_t)bh * 65536;
    const float* Vg = g_qkv + 12582912 + (size_t)bh * 65536;

    uint32_t qB = smem_u32(Qs), kB = smem_u32(Ks);
    uint32_t vB = smem_u32(VT), pB = smem_u32(Ps);

    // Load Q tile (64x64) once: tf32 + swizzle. 1024 float4 / 128 thr.
#pragma unroll
    for (int l = 0; l < 8; l++) {
        int i4 = tid + l * 128;
        int r = i4 >> 4, c = i4 & 15;
        float4 v = *(const float4*)(Qg + i4 * 4);
        uint32_t off = (uint32_t)((c >> 3) * 8192 + r * 128 + (c & 7) * 16);
        *(float4*)((char*)Qs + sw128(off)) = make_float4(to_tf32(v.x), to_tf32(v.y),
                                                         to_tf32(v.z), to_tf32(v.w));
    }

    float oacc[8][4];
#pragma unroll
    for (int nt = 0; nt < 8; nt++)
#pragma unroll
        for (int q = 0; q < 4; q++) oacc[nt][q] = 0.f;
    float mi0 = -3.0e38f, mi1 = -3.0e38f, li0 = 0.f, li1 = 0.f;

    for (int t = 0; t < 32; t++) {
        __syncthreads();
        // K tile (32x64): coalesced, tf32, swizzled
#pragma unroll
        for (int l = 0; l < 4; l++) {
            int i4 = tid + l * 128;
            int r = i4 >> 4, c = i4 & 15;
            float4 v = *(const float4*)(Kg + t * 2048 + i4 * 4);
            uint32_t off = (uint32_t)((c >> 3) * 4096 + r * 128 + (c & 7) * 16);
            *(float4*)((char*)Ks + sw128(off)) = make_float4(to_tf32(v.x), to_tf32(v.y),
                                                             to_tf32(v.z), to_tf32(v.w));
        }
        // V tile transposed into VT[d][kk]: lane gathers 16B along d (kk = lane),
        // so the 4 scalar stores land in distinct banks (kk varies across lanes).
#pragma unroll
        for (int l = 0; l < 4; l++) {
            int i4 = tid + l * 128;
            int kk = i4 & 31, d0 = (i4 >> 5) * 4;
            float4 v = *(const float4*)(Vg + t * 2048 + kk * 64 + d0);
            *(float*)((char*)VT + sw128((uint32_t)((d0 + 0) * 128 + kk * 4))) = to_tf32(v.x);
            *(float*)((char*)VT + sw128((uint32_t)((d0 + 1) * 128 + kk * 4))) = to_tf32(v.y);
            *(float*)((char*)VT + sw128((uint32_t)((d0 + 2) * 128 + kk * 4))) = to_tf32(v.z);
            *(float*)((char*)VT + sw128((uint32_t)((d0 + 3) * 128 + kk * 4))) = to_tf32(v.w);
        }
        __syncthreads();

        // S = Q @ K^T  (warp: m16 x n32, k=64)
        float sacc[4][4];
#pragma unroll
        for (int nt = 0; nt < 4; nt++)
#pragma unroll
            for (int q = 0; q < 4; q++) sacc[nt][q] = 0.f;
#pragma unroll
        for (int ks = 0; ks < 8; ks++) {
            uint32_t af[4], bf[2][4];
            uint32_t qoff = (uint32_t)((ks >> 2) * 8192 +
                            (rw + (blk & 1) * 8 + lr) * 128 + (ks & 3) * 32 + (blk >> 1) * 16);
            LDMX4(af, qB + sw128(qoff));
#pragma unroll
            for (int np = 0; np < 2; np++) {
                uint32_t koff = (uint32_t)((ks >> 2) * 4096 +
                                (np * 16 + (blk >> 1) * 8 + lr) * 128 + (ks & 3) * 32 + (blk & 1) * 16);
                LDMX4(bf[np], kB + sw128(koff));
            }
#pragma unroll
            for (int np = 0; np < 2; np++) {
                MMA_TF32(sacc[np * 2],     af, bf[np][0], bf[np][1]);
                MMA_TF32(sacc[np * 2 + 1], af, bf[np][2], bf[np][3]);
            }
        }

        // Online softmax. Thread holds rows rA=rw+(lane>>2) (c0,c1) and rA+8 (c2,c3).
        float mx0 = -3.0e38f, mx1 = -3.0e38f;
#pragma unroll
        for (int nt = 0; nt < 4; nt++) {
            sacc[nt][0] *= SCALE_F; sacc[nt][1] *= SCALE_F;
            sacc[nt][2] *= SCALE_F; sacc[nt][3] *= SCALE_F;
            mx0 = fmaxf(mx0, fmaxf(sacc[nt][0], sacc[nt][1]));
            mx1 = fmaxf(mx1, fmaxf(sacc[nt][2], sacc[nt][3]));
        }
        mx0 = fmaxf(mx0, __shfl_xor_sync(0xffffffffu, mx0, 1));
        mx0 = fmaxf(mx0, __shfl_xor_sync(0xffffffffu, mx0, 2));
        mx1 = fmaxf(mx1, __shfl_xor_sync(0xffffffffu, mx1, 1));
        mx1 = fmaxf(mx1, __shfl_xor_sync(0xffffffffu, mx1, 2));
        float mn0 = fmaxf(mi0, mx0), mn1 = fmaxf(mi1, mx1);
        float a0 = __expf(mi0 - mn0), a1 = __expf(mi1 - mn1);
        float s0 = 0.f, s1 = 0.f;
        int rA = rw + (lane >> 2);
        uint32_t colb = (uint32_t)((lane & 3) * 8);
#pragma unroll
        for (int nt = 0; nt < 4; nt++) {
            float p0 = to_tf32(__expf(sacc[nt][0] - mn0));
            float p1 = to_tf32(__expf(sacc[nt][1] - mn0));
            float p2 = to_tf32(__expf(sacc[nt][2] - mn1));
            float p3 = to_tf32(__expf(sacc[nt][3] - mn1));
            s0 += p0 + p1; s1 += p2 + p3;
            *(float2*)((char*)Ps + sw128((uint32_t)(rA * 128 + nt * 32) + colb)) = make_float2(p0, p1);
            *(float2*)((char*)Ps + sw128((uint32_t)((rA + 8) * 128 + nt * 32) + colb)) = make_float2(p2, p3);
        }
        s0 += __shfl_xor_sync(0xffffffffu, s0, 1);
        s0 += __shfl_xor_sync(0xffffffffu, s0, 2);
        s1 += __shfl_xor_sync(0xffffffffu, s1, 1);
        s1 += __shfl_xor_sync(0xffffffffu, s1, 2);
        li0 = li0 * a0 + s0; li1 = li1 * a1 + s1;
        mi0 = mn0; mi1 = mn1;
#pragma unroll
        for (int nt = 0; nt < 8; nt++) {
            oacc[nt][0] *= a0; oacc[nt][1] *= a0;
            oacc[nt][2] *= a1; oacc[nt][3] *= a1;
        }
        __syncwarp();

        // O += P @ V  (warp: m16 x n64, k=32). A from Ps (warp-private rows), B from VT.
#pragma unroll
        for (int ks = 0; ks < 4; ks++) {
            uint32_t af[4], vf[4][4];
            uint32_t poff = (uint32_t)((rw + (blk & 1) * 8 + lr) * 128 + ks * 32 + (blk >> 1) * 16);
            LDMX4(af, pB + sw128(poff));
#pragma unroll
            for (int vp = 0; vp < 4; vp++) {
                uint32_t voff = (uint32_t)((vp * 16 + (blk >> 1) * 8 + lr) * 128 + ks * 32 + (blk & 1) * 16);
                LDMX4(vf[vp], vB + sw128(voff));
            }
#pragma unroll
            for (int vp = 0; vp < 4; vp++) {
                MMA_TF32(oacc[vp * 2],     af, vf[vp][0], vf[vp][1]);
                MMA_TF32(oacc[vp * 2 + 1], af, vf[vp][2], vf[vp][3]);
            }
        }
    }

    // Normalize + write (head layout)
    float inv0 = 1.f / li0, inv1 = 1.f / li1;
    int rA = qt * 64 + rw + (lane >> 2);
    float* dst = g_att + (size_t)bh * 65536;
#pragma unroll
    for (int nt = 0; nt < 8; nt++) {
        int d = nt * 8 + (lane & 3) * 2;
        *(float2*)(dst + (size_t)rA * 64 + d)       = make_float2(oacc[nt][0] * inv0, oacc[nt][1] * inv0);
        *(float2*)(dst + (size_t)(rA + 8) * 64 + d) = make_float2(oacc[nt][2] * inv1, oacc[nt][3] * inv1);
    }
}

// ---------------------------------------------------------------------------
// Kernel 5: OUT = gather(g_att) @ Wp + bp  via mma.sync tf32 (verified R6)
// ---------------------------------------------------------------------------
__global__ __launch_bounds__(256) void gemm_out_mma(const float* __restrict__ bp,
                                                    float* __restrict__ out) {
    __shared__ __align__(128) float sA[128 * 32];
    __shared__ __align__(128) float sB[128 * 32];

    int tid = threadIdx.x;
    int warp = tid >> 5, lane = tid & 31;
    int warpM = warp >> 1, warpN = warp & 1;
    int rowBase = blockIdx.y * 128;
    int colBase = blockIdx.x * 128;
    const float* Bsrc = g_wpT + (size_t)colBase * 768;

    uint32_t aBase = smem_u32(sA), bBase = smem_u32(sB);
    int lr = lane & 7, blk = lane >> 3;
    uint32_t aOff = (uint32_t)((warpM * 32 + (blk & 1) * 8 + lr) * 128 + (blk >> 1) * 16);
    uint32_t bOff = (uint32_t)((warpN * 64 + (blk >> 1) * 8 + lr) * 128 + (blk & 1) * 16);

    float acc[2][8][4];
#pragma unroll
    for (int mt = 0; mt < 2; mt++)
#pragma unroll
        for (int nt = 0; nt < 8; nt++)
#pragma unroll
            for (int q = 0; q < 4; q++) acc[mt][nt][q] = 0.f;

    for (int it = 0; it < 24; it++) {
        int k0 = it * 32;
        int h = k0 >> 6, dbase = k0 & 63;
        float4 va[4], vb[4];
#pragma unroll
        for (int l = 0; l < 4; l++) {
            int idx = tid + l * 256;
            int row = idx >> 3, ci = idx & 7;
            int grow = rowBase + row;
            int b_ = grow >> 10, n = grow & 1023;
            va[l] = *(const float4*)(g_att + (size_t)(b_ * 12 + h) * 65536 + n * 64 + dbase + ci * 4);
            vb[l] = *(const float4*)(Bsrc + (size_t)row * 768 + k0 + ci * 4);
        }
        __syncthreads();
#pragma unroll
        for (int l = 0; l < 4; l++) {
            int idx = tid + l * 256;
            int row = idx >> 3, ci = idx & 7;
            uint32_t sw = sw128((uint32_t)(row * 128 + ci * 16));
            *(float4*)((char*)sA + sw) = make_float4(to_tf32(va[l].x), to_tf32(va[l].y),
                                                     to_tf32(va[l].z), to_tf32(va[l].w));
            *(float4*)((char*)sB + sw) = make_float4(to_tf32(vb[l].x), to_tf32(vb[l].y),
                                                     to_tf32(vb[l].z), to_tf32(vb[l].w));
        }
        __syncthreads();

#pragma unroll
        for (int ks = 0; ks < 4; ks++) {
            uint32_t af[2][4], bf[4][4];
#pragma unroll
            for (int mt = 0; mt < 2; mt++)
                LDMX4(af[mt], aBase + sw128(aOff + mt * 2048 + ks * 32));
#pragma unroll
            for (int np = 0; np < 4; np++)
                LDMX4(bf[np], bBase + sw128(bOff + np * 2048 + ks * 32));
#pragma unroll
            for (int mt = 0; mt < 2; mt++)
#pragma unroll
                for (int np = 0; np < 4; np++) {
                    MMA_TF32(acc[mt][np * 2],     af[mt], bf[np][0], bf[np][1]);
                    MMA_TF32(acc[mt][np * 2 + 1], af[mt], bf[np][2], bf[np][3]);
                }
        }
        __syncthreads();
    }

#pragma unroll
    for (int mt = 0; mt < 2; mt++) {
        int r0g = rowBase + warpM * 32 + mt * 16 + (lane >> 2);
#pragma unroll
        for (int nt = 0; nt < 8; nt++) {
            int col = colBase + warpN * 64 + nt * 8 + 2 * (lane & 3);
            float2 bb = *(const float2*)(bp + col);
            *(float2*)(out + (size_t)r0g * 768 + col) =
                make_float2(acc[mt][nt][0] + bb.x, acc[mt][nt][1] + bb.y);
            *(float2*)(out + (size_t)(r0g + 8) * 768 + col) =
                make_float2(acc[mt][nt][2] + bb.x, acc[mt][nt][3] + bb.y);
        }
    }
}

// ---------------------------------------------------------------------------
// Launch
// ---------------------------------------------------------------------------
extern "C" void kernel_launch(void* const* d_in, const int* in_sizes, int n_in,
                              void* d_out, int out_size) {
    const float* x   = (const float*)d_in[0];
    const float* Wq  = (const float*)d_in[1];
    const float* Wk  = (const float*)d_in[2];
    const float* Wv  = (const float*)d_in[3];
    const float* Wp  = (const float*)d_in[4];
    const float* bp  = (const float*)d_in[5];
    const float* laq = (const float*)d_in[6];
    const float* lbq = (const float*)d_in[7];
    const float* lak = (const float*)d_in[8];
    const float* lbk = (const float*)d_in[9];
    const float* lav = (const float*)d_in[10];
    const float* lbv = (const float*)d_in[11];
    const float* bw  = (const float*)d_in[12];
    float* out = (float*)d_out;

    build_weffT<<<dim3(24, 24, 3), 256>>>(Wq, Wk, Wv, laq, lbq, lak, lbk, lav, lbv, bw);
    transpose_wp<<<dim3(24, 24), 256>>>(Wp);
    gemm_qkv_mma<<<dim3(18, 64), 256>>>(x);
    flash_mma<<<dim3(16, 96), 128>>>();
    gemm_out_mma<<<dim3(6, 64), 256>>>(bp, out);
}

// round 13
// speedup vs baseline: 4.3082x; 1.6347x over previous
#include <cuda_runtime.h>
#include <cstdint>

// Problem constants: B=8, N=1024, C=768, H=12, HD=64, R=16
#define SCALE_F 0.125f

// ---------------------------------------------------------------------------
// Device scratch (no allocation allowed)
// ---------------------------------------------------------------------------
__device__ float g_weffT[3 * 768 * 768];     // effective W, tf32-rounded, [m][out_c][in_k]
__device__ float g_wpT  [768 * 768];         // Wp transposed, tf32-rounded
__device__ float g_x32  [8192 * 768];        // X, tf32-rounded
__device__ float g_qkv  [3 * 96 * 1024 * 64];// [m][b*12+h][n][d], tf32-rounded
__device__ float g_vT   [96 * 64 * 1024];    // V transposed: [bh][d][n]
__device__ float g_att  [96 * 1024 * 64];    // attention out, tf32-rounded

// ---------------------------------------------------------------------------
// Helpers (base-sm_103 legal: ldmatrix sm_75+, mma tf32 sm_80+, cp.async sm_80+)
// ---------------------------------------------------------------------------
__device__ __forceinline__ uint32_t smem_u32(const void* p) {
    uint32_t a;
    asm("{ .reg .u64 t; cvta.to.shared.u64 t, %1; cvt.u32.u64 %0, t; }" : "=r"(a) : "l"(p));
    return a;
}
__device__ __forceinline__ float to_tf32(float x) {
    float r;
    asm("cvt.rna.tf32.f32 %0, %1;" : "=f"(r) : "f"(x));
    return r;
}
__device__ __forceinline__ uint32_t sw128(uint32_t off) {
    return off ^ ((off >> 3) & 0x70);
}

#define LDMX4(r, addr)                                                            \
    asm volatile("ldmatrix.sync.aligned.m8n8.x4.shared.b16 {%0,%1,%2,%3}, [%4];"  \
        : "=r"((r)[0]), "=r"((r)[1]), "=r"((r)[2]), "=r"((r)[3]) : "r"(addr))

#define MMA_TF32(c, a, b0, b1)                                                    \
    asm volatile("mma.sync.aligned.m16n8k8.row.col.f32.tf32.tf32.f32 "            \
        "{%0,%1,%2,%3}, {%4,%5,%6,%7}, {%8,%9}, {%0,%1,%2,%3};"                   \
        : "+f"((c)[0]), "+f"((c)[1]), "+f"((c)[2]), "+f"((c)[3])                  \
        : "r"((a)[0]), "r"((a)[1]), "r"((a)[2]), "r"((a)[3]), "r"(b0), "r"(b1))

#define CP16(dst, src)                                                            \
    asm volatile("cp.async.cg.shared.global [%0], [%1], 16;" :: "r"(dst), "l"(src))
#define CP_COMMIT() asm volatile("cp.async.commit_group;" ::: "memory")
#define CP_WAIT1()  asm volatile("cp.async.wait_group 1;" ::: "memory")
#define CP_WAIT0()  asm volatile("cp.async.wait_group 0;" ::: "memory")

// ---------------------------------------------------------------------------
// Kernel 1: WeffT[m][c][k] = tf32(W[k][c] + bw[m]*(la@lb)[k][c])
// ---------------------------------------------------------------------------
__global__ __launch_bounds__(256) void build_weffT(
    const float* __restrict__ Wq, const float* __restrict__ Wk, const float* __restrict__ Wv,
    const float* __restrict__ laq, const float* __restrict__ lbq,
    const float* __restrict__ lak, const float* __restrict__ lbk,
    const float* __restrict__ lav, const float* __restrict__ lbv,
    const float* __restrict__ bw) {
    __shared__ float Wt[32][33];
    __shared__ float las[32][16];
    __shared__ float lbs[16][33];

    int mat = blockIdx.z;
    const float* W  = (mat == 0) ? Wq  : (mat == 1 ? Wk  : Wv);
    const float* la = (mat == 0) ? laq : (mat == 1 ? lak : lav);
    const float* lb = (mat == 0) ? lbq : (mat == 1 ? lbk : lbv);
    int k0 = blockIdx.x * 32, c0 = blockIdx.y * 32;
    int tid = threadIdx.x, tx = tid & 31, ty = tid >> 5;

#pragma unroll
    for (int i = 0; i < 4; i++) {
        int kk = ty + i * 8;
        Wt[kk][tx] = W[(k0 + kk) * 768 + c0 + tx];
    }
#pragma unroll
    for (int e = tid; e < 512; e += 256)
        las[e >> 4][e & 15] = la[(k0 + (e >> 4)) * 16 + (e & 15)];
#pragma unroll
    for (int e = tid; e < 512; e += 256)
        lbs[e >> 5][e & 31] = lb[(e >> 5) * 768 + c0 + (e & 31)];
    __syncthreads();

    float w = bw[mat];
#pragma unroll
    for (int i = 0; i < 4; i++) {
        int c = ty + i * 8;
        float s = 0.f;
#pragma unroll
        for (int r = 0; r < 16; r++) s += las[tx][r] * lbs[r][c];
        g_weffT[(size_t)mat * 589824 + (size_t)(c0 + c) * 768 + k0 + tx] =
            to_tf32(Wt[tx][c] + w * s);
    }
}

// ---------------------------------------------------------------------------
// Kernel 2: WpT[c][k] = tf32(Wp[k][c])
// ---------------------------------------------------------------------------
__global__ __launch_bounds__(256) void transpose_wp(const float* __restrict__ Wp) {
    __shared__ float Wt[32][33];
    int k0 = blockIdx.x * 32, c0 = blockIdx.y * 32;
    int tid = threadIdx.x, tx = tid & 31, ty = tid >> 5;
#pragma unroll
    for (int i = 0; i < 4; i++) {
        int kk = ty + i * 8;
        Wt[kk][tx] = Wp[(k0 + kk) * 768 + c0 + tx];
    }
    __syncthreads();
#pragma unroll
    for (int i = 0; i < 4; i++) {
        int c = ty + i * 8;
        g_wpT[(size_t)(c0 + c) * 768 + k0 + tx] = to_tf32(Wt[tx][c]);
    }
}

// ---------------------------------------------------------------------------
// Kernel 3: g_x32 = tf32(x).  1572864 float4; grid 6144 x 256
// ---------------------------------------------------------------------------
__global__ __launch_bounds__(256) void round_x(const float* __restrict__ x) {
    int i = blockIdx.x * 256 + threadIdx.x;
    float4 v = *(const float4*)(x + (size_t)i * 4);
    float4 r = make_float4(to_tf32(v.x), to_tf32(v.y), to_tf32(v.z), to_tf32(v.w));
    *(float4*)(g_x32 + (size_t)i * 4) = r;
}

// ---------------------------------------------------------------------------
// Kernel 4: QKV = X @ Weff, tf32 mma, cp.async 2-stage.  CTA tile 64x128, BK=32.
// grid (18, 128), block 256 (8 warps = 2(m) x 4(n); warp tile 32x32)
// ---------------------------------------------------------------------------
__global__ __launch_bounds__(256) void gemm_qkv_mma() {
    __shared__ __align__(128) float sA[2][2048];   // 64 x 32 per stage
    __shared__ __align__(128) float sB[2][4096];   // 128 x 32 per stage

    int tid = threadIdx.x;
    int warp = tid >> 5, lane = tid & 31;
    int warpM = warp >> 2, warpN = warp & 3;
    int rowBase = blockIdx.y * 64;
    int colBase = blockIdx.x * 128;
    int mat = colBase / 768;
    int cc  = colBase - mat * 768;
    const float* Asrc = g_x32;
    const float* Bsrc = g_weffT + (size_t)mat * 589824 + (size_t)cc * 768;

    uint32_t aBase = smem_u32(sA), bBase = smem_u32(sB);
    int lr = lane & 7, blk = lane >> 3;
    uint32_t aOff = (uint32_t)((warpM * 32 + (blk & 1) * 8 + lr) * 128 + (blk >> 1) * 16);
    uint32_t bOff = (uint32_t)((warpN * 32 + (blk >> 1) * 8 + lr) * 128 + (blk & 1) * 16);

    float acc[2][4][4];
#pragma unroll
    for (int mt = 0; mt < 2; mt++)
#pragma unroll
        for (int nt = 0; nt < 4; nt++)
#pragma unroll
            for (int q = 0; q < 4; q++) acc[mt][nt][q] = 0.f;

    for (int it = 0; it <= 24; it++) {
        if (it >= 2) __syncthreads();
        if (it < 24) {
            int k0 = it * 32;
            uint32_t sa = aBase + (it & 1) * 8192;
            uint32_t sb = bBase + (it & 1) * 16384;
#pragma unroll
            for (int l = 0; l < 2; l++) {
                int idx = tid + l * 256;
                int row = idx >> 3, ci = idx & 7;
                CP16(sa + sw128((uint32_t)(row * 128 + ci * 16)),
                     Asrc + (size_t)(rowBase + row) * 768 + k0 + ci * 4);
            }
#pragma unroll
            for (int l = 0; l < 4; l++) {
                int idx = tid + l * 256;
                int row = idx >> 3, ci = idx & 7;
                CP16(sb + sw128((uint32_t)(row * 128 + ci * 16)),
                     Bsrc + (size_t)row * 768 + k0 + ci * 4);
            }
            CP_COMMIT();
        }
        if (it == 0) continue;
        if (it < 24) CP_WAIT1(); else CP_WAIT0();
        __syncthreads();

        uint32_t sa = aBase + ((it - 1) & 1) * 8192;
        uint32_t sb = bBase + ((it - 1) & 1) * 16384;
#pragma unroll
        for (int ks = 0; ks < 4; ks++) {
            uint32_t af[2][4], bf[2][4];
#pragma unroll
            for (int mt = 0; mt < 2; mt++)
                LDMX4(af[mt], sa + sw128(aOff + mt * 2048 + ks * 32));
#pragma unroll
            for (int np = 0; np < 2; np++)
                LDMX4(bf[np], sb + sw128(bOff + np * 2048 + ks * 32));
#pragma unroll
            for (int mt = 0; mt < 2; mt++)
#pragma unroll
                for (int np = 0; np < 2; np++) {
                    MMA_TF32(acc[mt][np * 2],     af[mt], bf[np][0], bf[np][1]);
                    MMA_TF32(acc[mt][np * 2 + 1], af[mt], bf[np][2], bf[np][3]);
                }
        }
    }

    // epilogue: tf32-rounded into [m][b*12+h][n][d]
#pragma unroll
    for (int mt = 0; mt < 2; mt++) {
        int r0g = rowBase + warpM * 32 + mt * 16 + (lane >> 2);
        int b_ = r0g >> 10, n = r0g & 1023;
#pragma unroll
        for (int nt = 0; nt < 4; nt++) {
            int cIn = warpN * 32 + nt * 8 + 2 * (lane & 3);
            int h = cc / 64 + (cIn >> 6);
            int d = cIn & 63;
            float* dstBase = g_qkv + (size_t)((mat * 8 + b_) * 12 + h) * 65536;
            *(float2*)(dstBase + n * 64 + d) =
                make_float2(to_tf32(acc[mt][nt][0]), to_tf32(acc[mt][nt][1]));
            *(float2*)(dstBase + (n + 8) * 64 + d) =
                make_float2(to_tf32(acc[mt][nt][2]), to_tf32(acc[mt][nt][3]));
        }
    }
}

// ---------------------------------------------------------------------------
// Kernel 5: g_vT[bh][d][n] = g_qkv V[bh][n][d].  grid (32, 2, 96), block 256
// ---------------------------------------------------------------------------
__global__ __launch_bounds__(256) void transpose_v() {
    __shared__ float T[32][33];
    int n0 = blockIdx.x * 32, d0 = blockIdx.y * 32, bh = blockIdx.z;
    int tid = threadIdx.x, tx = tid & 31, ty = tid >> 5;
    const float* src = g_qkv + 12582912 + (size_t)bh * 65536;
#pragma unroll
    for (int i = 0; i < 4; i++)
        T[ty + i * 8][tx] = src[(size_t)(n0 + ty + i * 8) * 64 + d0 + tx];
    __syncthreads();
    float* dst = g_vT + (size_t)bh * 65536;
#pragma unroll
    for (int i = 0; i < 4; i++)
        dst[(size_t)(d0 + ty + i * 8) * 1024 + n0 + tx] = T[tx][ty + i * 8];
}

// ---------------------------------------------------------------------------
// Kernel 6: flash attention, tf32 mma, cp.async 2-stage K/VT, Q in registers.
// grid (16, 96), block 128 (4 warps, each m16). BM=64, BN=32.
// smem: sKV 32KB ring (Q staged here first), Ps 8KB.
// ---------------------------------------------------------------------------
__global__ __launch_bounds__(128, 4) void flash_mma() {
    __shared__ __align__(128) float sKV[8192];  // K stages @0,8KB; VT stages @16KB,24KB
    __shared__ __align__(128) float Ps[2048];   // [64 r][32 kk]

    int tid = threadIdx.x;
    int lane = tid & 31;
    int warp = tid >> 5;
    int rw = warp * 16;
    int blk = lane >> 3, lr = lane & 7;
    int bh = blockIdx.y, qt = blockIdx.x;
    const float* Qg  = g_qkv + (size_t)bh * 65536 + qt * 4096;
    const float* Kg  = g_qkv + 6291456 + (size_t)bh * 65536;
    const float* VTg = g_vT + (size_t)bh * 65536;

    uint32_t kvB = smem_u32(sKV), pB = smem_u32(Ps);

    // Stage Q (pre-rounded tf32) into sKV[0..16KB), load fragments, release.
#pragma unroll
    for (int l = 0; l < 8; l++) {
        int i4 = tid + l * 128;
        int r = i4 >> 4, c = i4 & 15;
        uint32_t off = (uint32_t)((c >> 3) * 8192 + r * 128 + (c & 7) * 16);
        *(float4*)((char*)sKV + sw128(off)) = *(const float4*)(Qg + i4 * 4);
    }
    __syncthreads();
    uint32_t qf[8][4];
#pragma unroll
    for (int ks = 0; ks < 8; ks++) {
        uint32_t qoff = (uint32_t)((ks >> 2) * 8192 +
                        (rw + (blk & 1) * 8 + lr) * 128 + (ks & 3) * 32 + (blk >> 1) * 16);
        LDMX4(qf[ks], kvB + sw128(qoff));
    }
    __syncthreads();   // Q staging region now free for the K/VT ring

    float oacc[8][4];
#pragma unroll
    for (int nt = 0; nt < 8; nt++)
#pragma unroll
        for (int q = 0; q < 4; q++) oacc[nt][q] = 0.f;
    float mi0 = -3.0e38f, mi1 = -3.0e38f, li0 = 0.f, li1 = 0.f;

    for (int t = 0; t <= 32; t++) {
        if (t >= 2) __syncthreads();
        if (t < 32) {
            uint32_t kDst = kvB + (t & 1) * 8192;
            uint32_t vDst = kvB + 16384 + (t & 1) * 8192;
#pragma unroll
            for (int l = 0; l < 4; l++) {
                int i4 = tid + l * 128;
                int r = i4 >> 4, c = i4 & 15;
                CP16(kDst + sw128((uint32_t)((c >> 3) * 4096 + r * 128 + (c & 7) * 16)),
                     Kg + t * 2048 + i4 * 4);
            }
#pragma unroll
            for (int l = 0; l < 4; l++) {
                int i4 = tid + l * 128;
                int d = i4 >> 3, ck = i4 & 7;
                CP16(vDst + sw128((uint32_t)(d * 128 + ck * 16)),
                     VTg + (size_t)d * 1024 + t * 32 + ck * 4);
            }
            CP_COMMIT();
        }
        if (t == 0) continue;
        if (t < 32) CP_WAIT1(); else CP_WAIT0();
        __syncthreads();

        uint32_t kS = kvB + ((t - 1) & 1) * 8192;
        uint32_t vS = kvB + 16384 + ((t - 1) & 1) * 8192;

        // S = Q @ K^T  (warp: m16 x n32, k=64)
        float sacc[4][4];
#pragma unroll
        for (int nt = 0; nt < 4; nt++)
#pragma unroll
            for (int q = 0; q < 4; q++) sacc[nt][q] = 0.f;
#pragma unroll
        for (int ks = 0; ks < 8; ks++) {
#pragma unroll
            for (int np = 0; np < 2; np++) {
                uint32_t bf[4];
                uint32_t koff = (uint32_t)((ks >> 2) * 4096 +
                                (np * 16 + (blk >> 1) * 8 + lr) * 128 + (ks & 3) * 32 + (blk & 1) * 16);
                LDMX4(bf, kS + sw128(koff));
                MMA_TF32(sacc[np * 2],     qf[ks], bf[0], bf[1]);
                MMA_TF32(sacc[np * 2 + 1], qf[ks], bf[2], bf[3]);
            }
        }

        // Online softmax (thread rows rA, rA+8; 4 lanes per row)
        float mx0 = -3.0e38f, mx1 = -3.0e38f;
#pragma unroll
        for (int nt = 0; nt < 4; nt++) {
            sacc[nt][0] *= SCALE_F; sacc[nt][1] *= SCALE_F;
            sacc[nt][2] *= SCALE_F; sacc[nt][3] *= SCALE_F;
            mx0 = fmaxf(mx0, fmaxf(sacc[nt][0], sacc[nt][1]));
            mx1 = fmaxf(mx1, fmaxf(sacc[nt][2], sacc[nt][3]));
        }
        mx0 = fmaxf(mx0, __shfl_xor_sync(0xffffffffu, mx0, 1));
        mx0 = fmaxf(mx0, __shfl_xor_sync(0xffffffffu, mx0, 2));
        mx1 = fmaxf(mx1, __shfl_xor_sync(0xffffffffu, mx1, 1));
        mx1 = fmaxf(mx1, __shfl_xor_sync(0xffffffffu, mx1, 2));
        float mn0 = fmaxf(mi0, mx0), mn1 = fmaxf(mi1, mx1);
        float a0 = __expf(mi0 - mn0), a1 = __expf(mi1 - mn1);
        float s0 = 0.f, s1 = 0.f;
        int rA = rw + (lane >> 2);
        uint32_t colb = (uint32_t)((lane & 3) * 8);
#pragma unroll
        for (int nt = 0; nt < 4; nt++) {
            float p0 = to_tf32(__expf(sacc[nt][0] - mn0));
            float p1 = to_tf32(__expf(sacc[nt][1] - mn0));
            float p2 = to_tf32(__expf(sacc[nt][2] - mn1));
            float p3 = to_tf32(__expf(sacc[nt][3] - mn1));
            s0 += p0 + p1; s1 += p2 + p3;
            *(float2*)((char*)Ps + sw128((uint32_t)(rA * 128 + nt * 32) + colb)) = make_float2(p0, p1);
            *(float2*)((char*)Ps + sw128((uint32_t)((rA + 8) * 128 + nt * 32) + colb)) = make_float2(p2, p3);
        }
        s0 += __shfl_xor_sync(0xffffffffu, s0, 1);
        s0 += __shfl_xor_sync(0xffffffffu, s0, 2);
        s1 += __shfl_xor_sync(0xffffffffu, s1, 1);
        s1 += __shfl_xor_sync(0xffffffffu, s1, 2);
        li0 = li0 * a0 + s0; li1 = li1 * a1 + s1;
        mi0 = mn0; mi1 = mn1;
#pragma unroll
        for (int nt = 0; nt < 8; nt++) {
            oacc[nt][0] *= a0; oacc[nt][1] *= a0;
            oacc[nt][2] *= a1; oacc[nt][3] *= a1;
        }
        __syncwarp();

        // O += P @ V  (warp: m16 x n64, k=32)
#pragma unroll
        for (int ks = 0; ks < 4; ks++) {
            uint32_t af[4];
            uint32_t poff = (uint32_t)((rw + (blk & 1) * 8 + lr) * 128 + ks * 32 + (blk >> 1) * 16);
            LDMX4(af, pB + sw128(poff));
#pragma unroll
            for (int vp = 0; vp < 4; vp++) {
                uint32_t vf[4];
                uint32_t voff = (uint32_t)((vp * 16 + (blk >> 1) * 8 + lr) * 128 + ks * 32 + (blk & 1) * 16);
                LDMX4(vf, vS + sw128(voff));
                MMA_TF32(oacc[vp * 2],     af, vf[0], vf[1]);
                MMA_TF32(oacc[vp * 2 + 1], af, vf[2], vf[3]);
            }
        }
    }

    // Normalize + write (tf32-rounded, head layout)
    float inv0 = 1.f / li0, inv1 = 1.f / li1;
    int rA = qt * 64 + rw + (lane >> 2);
    float* dst = g_att + (size_t)bh * 65536;
#pragma unroll
    for (int nt = 0; nt < 8; nt++) {
        int d = nt * 8 + (lane & 3) * 2;
        *(float2*)(dst + (size_t)rA * 64 + d) =
            make_float2(to_tf32(oacc[nt][0] * inv0), to_tf32(oacc[nt][1] * inv0));
        *(float2*)(dst + (size_t)(rA + 8) * 64 + d) =
            make_float2(to_tf32(oacc[nt][2] * inv1), to_tf32(oacc[nt][3] * inv1));
    }
}

// ---------------------------------------------------------------------------
// Kernel 7: OUT = gather(g_att) @ Wp + bp, tf32 mma, cp.async 2-stage.
// CTA tile 64x128.  grid (6, 128), block 256
// ---------------------------------------------------------------------------
__global__ __launch_bounds__(256) void gemm_out_mma(const float* __restrict__ bp,
                                                    float* __restrict__ out) {
    __shared__ __align__(128) float sA[2][2048];
    __shared__ __align__(128) float sB[2][4096];

    int tid = threadIdx.x;
    int warp = tid >> 5, lane = tid & 31;
    int warpM = warp >> 2, warpN = warp & 3;
    int rowBase = blockIdx.y * 64;
    int colBase = blockIdx.x * 128;
    const float* Bsrc = g_wpT + (size_t)colBase * 768;

    uint32_t aBase = smem_u32(sA), bBase = smem_u32(sB);
    int lr = lane & 7, blk = lane >> 3;
    uint32_t aOff = (uint32_t)((warpM * 32 + (blk & 1) * 8 + lr) * 128 + (blk >> 1) * 16);
    uint32_t bOff = (uint32_t)((warpN * 32 + (blk >> 1) * 8 + lr) * 128 + (blk & 1) * 16);

    float acc[2][4][4];
#pragma unroll
    for (int mt = 0; mt < 2; mt++)
#pragma unroll
        for (int nt = 0; nt < 4; nt++)
#pragma unroll
            for (int q = 0; q < 4; q++) acc[mt][nt][q] = 0.f;

    for (int it = 0; it <= 24; it++) {
        if (it >= 2) __syncthreads();
        if (it < 24) {
            int k0 = it * 32;
            int h = k0 >> 6, dbase = k0 & 63;
            uint32_t sa = aBase + (it & 1) * 8192;
            uint32_t sb = bBase + (it & 1) * 16384;
#pragma unroll
            for (int l = 0; l < 2; l++) {
                int idx = tid + l * 256;
                int row = idx >> 3, ci = idx & 7;
                int grow = rowBase + row;
                int b_ = grow >> 10, n = grow & 1023;
                CP16(sa + sw128((uint32_t)(row * 128 + ci * 16)),
                     g_att + (size_t)(b_ * 12 + h) * 65536 + n * 64 + dbase + ci * 4);
            }
#pragma unroll
            for (int l = 0; l < 4; l++) {
                int idx = tid + l * 256;
                int row = idx >> 3, ci = idx & 7;
                CP16(sb + sw128((uint32_t)(row * 128 + ci * 16)),
                     Bsrc + (size_t)row * 768 + k0 + ci * 4);
            }
            CP_COMMIT();
        }
        if (it == 0) continue;
        if (it < 24) CP_WAIT1(); else CP_WAIT0();
        __syncthreads();

        uint32_t sa = aBase + ((it - 1) & 1) * 8192;
        uint32_t sb = bBase + ((it - 1) & 1) * 16384;
#pragma unroll
        for (int ks = 0; ks < 4; ks++) {
            uint32_t af[2][4], bf[2][4];
#pragma unroll
            for (int mt = 0; mt < 2; mt++)
                LDMX4(af[mt], sa + sw128(aOff + mt * 2048 + ks * 32));
#pragma unroll
            for (int np = 0; np < 2; np++)
                LDMX4(bf[np], sb + sw128(bOff + np * 2048 + ks * 32));
#pragma unroll
            for (int mt = 0; mt < 2; mt++)
#pragma unroll
                for (int np = 0; np < 2; np++) {
                    MMA_TF32(acc[mt][np * 2],     af[mt], bf[np][0], bf[np][1]);
                    MMA_TF32(acc[mt][np * 2 + 1], af[mt], bf[np][2], bf[np][3]);
                }
        }
    }

#pragma unroll
    for (int mt = 0; mt < 2; mt++) {
        int r0g = rowBase + warpM * 32 + mt * 16 + (lane >> 2);
#pragma unroll
        for (int nt = 0; nt < 4; nt++) {
            int col = colBase + warpN * 32 + nt * 8 + 2 * (lane & 3);
            float2 bb = *(const float2*)(bp + col);
            *(float2*)(out + (size_t)r0g * 768 + col) =
                make_float2(acc[mt][nt][0] + bb.x, acc[mt][nt][1] + bb.y);
            *(float2*)(out + (size_t)(r0g + 8) * 768 + col) =
                make_float2(acc[mt][nt][2] + bb.x, acc[mt][nt][3] + bb.y);
        }
    }
}

// ---------------------------------------------------------------------------
// Launch
// ---------------------------------------------------------------------------
extern "C" void kernel_launch(void* const* d_in, const int* in_sizes, int n_in,
                              void* d_out, int out_size) {
    const float* x   = (const float*)d_in[0];
    const float* Wq  = (const float*)d_in[1];
    const float* Wk  = (const float*)d_in[2];
    const float* Wv  = (const float*)d_in[3];
    const float* Wp  = (const float*)d_in[4];
    const float* bp  = (const float*)d_in[5];
    const float* laq = (const float*)d_in[6];
    const float* lbq = (const float*)d_in[7];
    const float* lak = (const float*)d_in[8];
    const float* lbk = (const float*)d_in[9];
    const float* lav = (const float*)d_in[10];
    const float* lbv = (const float*)d_in[11];
    const float* bw  = (const float*)d_in[12];
    float* out = (float*)d_out;

    build_weffT<<<dim3(24, 24, 3), 256>>>(Wq, Wk, Wv, laq, lbq, lak, lbk, lav, lbv, bw);
    transpose_wp<<<dim3(24, 24), 256>>>(Wp);
    round_x<<<6144, 256>>>(x);
    gemm_qkv_mma<<<dim3(18, 128), 256>>>();
    transpose_v<<<dim3(32, 2, 96), 256>>>();
    flash_mma<<<dim3(16, 96), 128>>>();
    gemm_out_mma<<<dim3(6, 128), 256>>>(bp, out);
}

// round 15
// speedup vs baseline: 4.4538x; 1.0338x over previous
#include <cuda_runtime.h>
#include <cstdint>

// Problem constants: B=8, N=1024, C=768, H=12, HD=64, R=16
#define SCALE_F 0.125f

// ---------------------------------------------------------------------------
// Device scratch (no allocation allowed)
// ---------------------------------------------------------------------------
__device__ float g_weffT[3 * 768 * 768];     // effective W, tf32-rounded, [m][out_c][in_k]
__device__ float g_wpT  [768 * 768];         // Wp transposed, tf32-rounded
__device__ float g_x32  [8192 * 768];        // X, tf32-rounded
__device__ float g_qkv  [3 * 96 * 1024 * 64];// [m][b*12+h][n][d], tf32-rounded
__device__ float g_vT   [96 * 64 * 1024];    // V transposed: [bh][d][n]
__device__ float g_att  [96 * 1024 * 64];    // attention out, tf32-rounded

// ---------------------------------------------------------------------------
// Helpers (base-sm_103 legal: ldmatrix sm_75+, mma tf32 sm_80+, cp.async sm_80+)
// ---------------------------------------------------------------------------
__device__ __forceinline__ uint32_t smem_u32(const void* p) {
    uint32_t a;
    asm("{ .reg .u64 t; cvta.to.shared.u64 t, %1; cvt.u32.u64 %0, t; }" : "=r"(a) : "l"(p));
    return a;
}
__device__ __forceinline__ float to_tf32(float x) {
    float r;
    asm("cvt.rna.tf32.f32 %0, %1;" : "=f"(r) : "f"(x));
    return r;
}
__device__ __forceinline__ uint32_t sw128(uint32_t off) {
    return off ^ ((off >> 3) & 0x70);
}

#define LDMX4(r, addr)                                                            \
    asm volatile("ldmatrix.sync.aligned.m8n8.x4.shared.b16 {%0,%1,%2,%3}, [%4];"  \
        : "=r"((r)[0]), "=r"((r)[1]), "=r"((r)[2]), "=r"((r)[3]) : "r"(addr))

#define MMA_TF32(c, a, b0, b1)                                                    \
    asm volatile("mma.sync.aligned.m16n8k8.row.col.f32.tf32.tf32.f32 "            \
        "{%0,%1,%2,%3}, {%4,%5,%6,%7}, {%8,%9}, {%0,%1,%2,%3};"                   \
        : "+f"((c)[0]), "+f"((c)[1]), "+f"((c)[2]), "+f"((c)[3])                  \
        : "r"((a)[0]), "r"((a)[1]), "r"((a)[2]), "r"((a)[3]), "r"(b0), "r"(b1))

#define CP16(dst, src)                                                            \
    asm volatile("cp.async.cg.shared.global [%0], [%1], 16;" :: "r"(dst), "l"(src))
#define CP_COMMIT() asm volatile("cp.async.commit_group;" ::: "memory")
#define CP_WAIT1()  asm volatile("cp.async.wait_group 1;" ::: "memory")
#define CP_WAIT0()  asm volatile("cp.async.wait_group 0;" ::: "memory")

// ---------------------------------------------------------------------------
// Kernel 1: WeffT[m][c][k] = tf32(W[k][c] + bw[m]*(la@lb)[k][c])
// ---------------------------------------------------------------------------
__global__ __launch_bounds__(256) void build_weffT(
    const float* __restrict__ Wq, const float* __restrict__ Wk, const float* __restrict__ Wv,
    const float* __restrict__ laq, const float* __restrict__ lbq,
    const float* __restrict__ lak, const float* __restrict__ lbk,
    const float* __restrict__ lav, const float* __restrict__ lbv,
    const float* __restrict__ bw) {
    __shared__ float Wt[32][33];
    __shared__ float las[32][16];
    __shared__ float lbs[16][33];

    int mat = blockIdx.z;
    const float* W  = (mat == 0) ? Wq  : (mat == 1 ? Wk  : Wv);
    const float* la = (mat == 0) ? laq : (mat == 1 ? lak : lav);
    const float* lb = (mat == 0) ? lbq : (mat == 1 ? lbk : lbv);
    int k0 = blockIdx.x * 32, c0 = blockIdx.y * 32;
    int tid = threadIdx.x, tx = tid & 31, ty = tid >> 5;

#pragma unroll
    for (int i = 0; i < 4; i++) {
        int kk = ty + i * 8;
        Wt[kk][tx] = W[(k0 + kk) * 768 + c0 + tx];
    }
#pragma unroll
    for (int e = tid; e < 512; e += 256)
        las[e >> 4][e & 15] = la[(k0 + (e >> 4)) * 16 + (e & 15)];
#pragma unroll
    for (int e = tid; e < 512; e += 256)
        lbs[e >> 5][e & 31] = lb[(e >> 5) * 768 + c0 + (e & 31)];
    __syncthreads();

    float w = bw[mat];
#pragma unroll
    for (int i = 0; i < 4; i++) {
        int c = ty + i * 8;
        float s = 0.f;
#pragma unroll
        for (int r = 0; r < 16; r++) s += las[tx][r] * lbs[r][c];
        g_weffT[(size_t)mat * 589824 + (size_t)(c0 + c) * 768 + k0 + tx] =
            to_tf32(Wt[tx][c] + w * s);
    }
}

// ---------------------------------------------------------------------------
// Kernel 2: WpT[c][k] = tf32(Wp[k][c])
// ---------------------------------------------------------------------------
__global__ __launch_bounds__(256) void transpose_wp(const float* __restrict__ Wp) {
    __shared__ float Wt[32][33];
    int k0 = blockIdx.x * 32, c0 = blockIdx.y * 32;
    int tid = threadIdx.x, tx = tid & 31, ty = tid >> 5;
#pragma unroll
    for (int i = 0; i < 4; i++) {
        int kk = ty + i * 8;
        Wt[kk][tx] = Wp[(k0 + kk) * 768 + c0 + tx];
    }
    __syncthreads();
#pragma unroll
    for (int i = 0; i < 4; i++) {
        int c = ty + i * 8;
        g_wpT[(size_t)(c0 + c) * 768 + k0 + tx] = to_tf32(Wt[tx][c]);
    }
}

// ---------------------------------------------------------------------------
// Kernel 3: g_x32 = tf32(x).  1572864 float4; grid 6144 x 256
// ---------------------------------------------------------------------------
__global__ __launch_bounds__(256) void round_x(const float* __restrict__ x) {
    int i = blockIdx.x * 256 + threadIdx.x;
    float4 v = *(const float4*)(x + (size_t)i * 4);
    float4 r = make_float4(to_tf32(v.x), to_tf32(v.y), to_tf32(v.z), to_tf32(v.w));
    *(float4*)(g_x32 + (size_t)i * 4) = r;
}

// ---------------------------------------------------------------------------
// Kernel 4: QKV = X @ Weff, tf32 mma, cp.async 2-stage.
// CTA tile 64x128, BK=32.  grid (18, 128), block 128 (4 warps = 2m x 2n;
// warp tile 32x64 — R6-verified fragment shape, lower LDSM:MMA ratio)
// ---------------------------------------------------------------------------
__global__ __launch_bounds__(128, 3) void gemm_qkv_mma() {
    __shared__ __align__(128) float sA[2][2048];   // 64 x 32 per stage
    __shared__ __align__(128) float sB[2][4096];   // 128 x 32 per stage

    int tid = threadIdx.x;
    int warp = tid >> 5, lane = tid & 31;
    int warpM = warp >> 1, warpN = warp & 1;
    int rowBase = blockIdx.y * 64;
    int colBase = blockIdx.x * 128;
    int mat = colBase / 768;
    int cc  = colBase - mat * 768;
    const float* Asrc = g_x32;
    const float* Bsrc = g_weffT + (size_t)mat * 589824 + (size_t)cc * 768;

    uint32_t aBase = smem_u32(sA), bBase = smem_u32(sB);
    int lr = lane & 7, blk = lane >> 3;
    uint32_t aOff = (uint32_t)((warpM * 32 + (blk & 1) * 8 + lr) * 128 + (blk >> 1) * 16);
    uint32_t bOff = (uint32_t)((warpN * 64 + (blk >> 1) * 8 + lr) * 128 + (blk & 1) * 16);

    float acc[2][8][4];
#pragma unroll
    for (int mt = 0; mt < 2; mt++)
#pragma unroll
        for (int nt = 0; nt < 8; nt++)
#pragma unroll
            for (int q = 0; q < 4; q++) acc[mt][nt][q] = 0.f;

    for (int it = 0; it <= 24; it++) {
        if (it >= 2) __syncthreads();
        if (it < 24) {
            int k0 = it * 32;
            uint32_t sa = aBase + (it & 1) * 8192;
            uint32_t sb = bBase + (it & 1) * 16384;
#pragma unroll
            for (int l = 0; l < 4; l++) {
                int idx = tid + l * 128;
                int row = idx >> 3, ci = idx & 7;
                CP16(sa + sw128((uint32_t)(row * 128 + ci * 16)),
                     Asrc + (size_t)(rowBase + row) * 768 + k0 + ci * 4);
            }
#pragma unroll
            for (int l = 0; l < 8; l++) {
                int idx = tid + l * 128;
                int row = idx >> 3, ci = idx & 7;
                CP16(sb + sw128((uint32_t)(row * 128 + ci * 16)),
                     Bsrc + (size_t)row * 768 + k0 + ci * 4);
            }
            CP_COMMIT();
        }
        if (it == 0) continue;
        if (it < 24) CP_WAIT1(); else CP_WAIT0();
        __syncthreads();

        uint32_t sa = aBase + ((it - 1) & 1) * 8192;
        uint32_t sb = bBase + ((it - 1) & 1) * 16384;
#pragma unroll
        for (int ks = 0; ks < 4; ks++) {
            uint32_t af[2][4], bf[4][4];
#pragma unroll
            for (int mt = 0; mt < 2; mt++)
                LDMX4(af[mt], sa + sw128(aOff + mt * 2048 + ks * 32));
#pragma unroll
            for (int np = 0; np < 4; np++)
                LDMX4(bf[np], sb + sw128(bOff + np * 2048 + ks * 32));
#pragma unroll
            for (int mt = 0; mt < 2; mt++)
#pragma unroll
                for (int np = 0; np < 4; np++) {
                    MMA_TF32(acc[mt][np * 2],     af[mt], bf[np][0], bf[np][1]);
                    MMA_TF32(acc[mt][np * 2 + 1], af[mt], bf[np][2], bf[np][3]);
                }
        }
    }

    // epilogue: tf32-rounded into [m][b*12+h][n][d]
#pragma unroll
    for (int mt = 0; mt < 2; mt++) {
        int r0g = rowBase + warpM * 32 + mt * 16 + (lane >> 2);
        int b_ = r0g >> 10, n = r0g & 1023;
#pragma unroll
        for (int nt = 0; nt < 8; nt++) {
            int cIn = warpN * 64 + nt * 8 + 2 * (lane & 3);
            int h = cc / 64 + (cIn >> 6);
            int d = cIn & 63;
            float* dstBase = g_qkv + (size_t)((mat * 8 + b_) * 12 + h) * 65536;
            *(float2*)(dstBase + n * 64 + d) =
                make_float2(to_tf32(acc[mt][nt][0]), to_tf32(acc[mt][nt][1]));
            *(float2*)(dstBase + (n + 8) * 64 + d) =
                make_float2(to_tf32(acc[mt][nt][2]), to_tf32(acc[mt][nt][3]));
        }
    }
}

// ---------------------------------------------------------------------------
// Kernel 5: g_vT[bh][d][n] = g_qkv V[bh][n][d].  grid (32, 2, 96), block 256
// ---------------------------------------------------------------------------
__global__ __launch_bounds__(256) void transpose_v() {
    __shared__ float T[32][33];
    int n0 = blockIdx.x * 32, d0 = blockIdx.y * 32, bh = blockIdx.z;
    int tid = threadIdx.x, tx = tid & 31, ty = tid >> 5;
    const float* src = g_qkv + 12582912 + (size_t)bh * 65536;
#pragma unroll
    for (int i = 0; i < 4; i++)
        T[ty + i * 8][tx] = src[(size_t)(n0 + ty + i * 8) * 64 + d0 + tx];
    __syncthreads();
    float* dst = g_vT + (size_t)bh * 65536;
#pragma unroll
    for (int i = 0; i < 4; i++)
        dst[(size_t)(d0 + ty + i * 8) * 1024 + n0 + tx] = T[tx][ty + i * 8];
}

// ---------------------------------------------------------------------------
// Kernel 6: flash attention, tf32 mma, cp.async 2-stage K/VT, Q in registers.
// grid (16, 96), block 128 (4 warps, each m16). BM=64, BN=32.  (unchanged R13)
// ---------------------------------------------------------------------------
__global__ __launch_bounds__(128, 4) void flash_mma() {
    __shared__ __align__(128) float sKV[8192];  // K stages @0,8KB; VT stages @16KB,24KB
    __shared__ __align__(128) float Ps[2048];   // [64 r][32 kk]

    int tid = threadIdx.x;
    int lane = tid & 31;
    int warp = tid >> 5;
    int rw = warp * 16;
    int blk = lane >> 3, lr = lane & 7;
    int bh = blockIdx.y, qt = blockIdx.x;
    const float* Qg  = g_qkv + (size_t)bh * 65536 + qt * 4096;
    const float* Kg  = g_qkv + 6291456 + (size_t)bh * 65536;
    const float* VTg = g_vT + (size_t)bh * 65536;

    uint32_t kvB = smem_u32(sKV), pB = smem_u32(Ps);

    // Stage Q (pre-rounded tf32) into sKV[0..16KB), load fragments, release.
#pragma unroll
    for (int l = 0; l < 8; l++) {
        int i4 = tid + l * 128;
        int r = i4 >> 4, c = i4 & 15;
        uint32_t off = (uint32_t)((c >> 3) * 8192 + r * 128 + (c & 7) * 16);
        *(float4*)((char*)sKV + sw128(off)) = *(const float4*)(Qg + i4 * 4);
    }
    __syncthreads();
    uint32_t qf[8][4];
#pragma unroll
    for (int ks = 0; ks < 8; ks++) {
        uint32_t qoff = (uint32_t)((ks >> 2) * 8192 +
                        (rw + (blk & 1) * 8 + lr) * 128 + (ks & 3) * 32 + (blk >> 1) * 16);
        LDMX4(qf[ks], kvB + sw128(qoff));
    }
    __syncthreads();   // Q staging region now free for the K/VT ring

    float oacc[8][4];
#pragma unroll
    for (int nt = 0; nt < 8; nt++)
#pragma unroll
        for (int q = 0; q < 4; q++) oacc[nt][q] = 0.f;
    float mi0 = -3.0e38f, mi1 = -3.0e38f, li0 = 0.f, li1 = 0.f;

    for (int t = 0; t <= 32; t++) {
        if (t >= 2) __syncthreads();
        if (t < 32) {
            uint32_t kDst = kvB + (t & 1) * 8192;
            uint32_t vDst = kvB + 16384 + (t & 1) * 8192;
#pragma unroll
            for (int l = 0; l < 4; l++) {
                int i4 = tid + l * 128;
                int r = i4 >> 4, c = i4 & 15;
                CP16(kDst + sw128((uint32_t)((c >> 3) * 4096 + r * 128 + (c & 7) * 16)),
                     Kg + t * 2048 + i4 * 4);
            }
#pragma unroll
            for (int l = 0; l < 4; l++) {
                int i4 = tid + l * 128;
                int d = i4 >> 3, ck = i4 & 7;
                CP16(vDst + sw128((uint32_t)(d * 128 + ck * 16)),
                     VTg + (size_t)d * 1024 + t * 32 + ck * 4);
            }
            CP_COMMIT();
        }
        if (t == 0) continue;
        if (t < 32) CP_WAIT1(); else CP_WAIT0();
        __syncthreads();

        uint32_t kS = kvB + ((t - 1) & 1) * 8192;
        uint32_t vS = kvB + 16384 + ((t - 1) & 1) * 8192;

        // S = Q @ K^T  (warp: m16 x n32, k=64)
        float sacc[4][4];
#pragma unroll
        for (int nt = 0; nt < 4; nt++)
#pragma unroll
            for (int q = 0; q < 4; q++) sacc[nt][q] = 0.f;
#pragma unroll
        for (int ks = 0; ks < 8; ks++) {
#pragma unroll
            for (int np = 0; np < 2; np++) {
                uint32_t bf[4];
                uint32_t koff = (uint32_t)((ks >> 2) * 4096 +
                                (np * 16 + (blk >> 1) * 8 + lr) * 128 + (ks & 3) * 32 + (blk & 1) * 16);
                LDMX4(bf, kS + sw128(koff));
                MMA_TF32(sacc[np * 2],     qf[ks], bf[0], bf[1]);
                MMA_TF32(sacc[np * 2 + 1], qf[ks], bf[2], bf[3]);
            }
        }

        // Online softmax (thread rows rA, rA+8; 4 lanes per row)
        float mx0 = -3.0e38f, mx1 = -3.0e38f;
#pragma unroll
        for (int nt = 0; nt < 4; nt++) {
            sacc[nt][0] *= SCALE_F; sacc[nt][1] *= SCALE_F;
            sacc[nt][2] *= SCALE_F; sacc[nt][3] *= SCALE_F;
            mx0 = fmaxf(mx0, fmaxf(sacc[nt][0], sacc[nt][1]));
            mx1 = fmaxf(mx1, fmaxf(sacc[nt][2], sacc[nt][3]));
        }
        mx0 = fmaxf(mx0, __shfl_xor_sync(0xffffffffu, mx0, 1));
        mx0 = fmaxf(mx0, __shfl_xor_sync(0xffffffffu, mx0, 2));
        mx1 = fmaxf(mx1, __shfl_xor_sync(0xffffffffu, mx1, 1));
        mx1 = fmaxf(mx1, __shfl_xor_sync(0xffffffffu, mx1, 2));
        float mn0 = fmaxf(mi0, mx0), mn1 = fmaxf(mi1, mx1);
        float a0 = __expf(mi0 - mn0), a1 = __expf(mi1 - mn1);
        float s0 = 0.f, s1 = 0.f;
        int rA = rw + (lane >> 2);
        uint32_t colb = (uint32_t)((lane & 3) * 8);
#pragma unroll
        for (int nt = 0; nt < 4; nt++) {
            float p0 = to_tf32(__expf(sacc[nt][0] - mn0));
            float p1 = to_tf32(__expf(sacc[nt][1] - mn0));
            float p2 = to_tf32(__expf(sacc[nt][2] - mn1));
            float p3 = to_tf32(__expf(sacc[nt][3] - mn1));
            s0 += p0 + p1; s1 += p2 + p3;
            *(float2*)((char*)Ps + sw128((uint32_t)(rA * 128 + nt * 32) + colb)) = make_float2(p0, p1);
            *(float2*)((char*)Ps + sw128((uint32_t)((rA + 8) * 128 + nt * 32) + colb)) = make_float2(p2, p3);
        }
        s0 += __shfl_xor_sync(0xffffffffu, s0, 1);
        s0 += __shfl_xor_sync(0xffffffffu, s0, 2);
        s1 += __shfl_xor_sync(0xffffffffu, s1, 1);
        s1 += __shfl_xor_sync(0xffffffffu, s1, 2);
        li0 = li0 * a0 + s0; li1 = li1 * a1 + s1;
        mi0 = mn0; mi1 = mn1;
#pragma unroll
        for (int nt = 0; nt < 8; nt++) {
            oacc[nt][0] *= a0; oacc[nt][1] *= a0;
            oacc[nt][2] *= a1; oacc[nt][3] *= a1;
        }
        __syncwarp();

        // O += P @ V  (warp: m16 x n64, k=32)
#pragma unroll
        for (int ks = 0; ks < 4; ks++) {
            uint32_t af[4];
            uint32_t poff = (uint32_t)((rw + (blk & 1) * 8 + lr) * 128 + ks * 32 + (blk >> 1) * 16);
            LDMX4(af, pB + sw128(poff));
#pragma unroll
            for (int vp = 0; vp < 4; vp++) {
                uint32_t vf[4];
                uint32_t voff = (uint32_t)((vp * 16 + (blk >> 1) * 8 + lr) * 128 + ks * 32 + (blk & 1) * 16);
                LDMX4(vf, vS + sw128(voff));
                MMA_TF32(oacc[vp * 2],     af, vf[0], vf[1]);
                MMA_TF32(oacc[vp * 2 + 1], af, vf[2], vf[3]);
            }
        }
    }

    // Normalize + write (tf32-rounded, head layout)
    float inv0 = 1.f / li0, inv1 = 1.f / li1;
    int rA = qt * 64 + rw + (lane >> 2);
    float* dst = g_att + (size_t)bh * 65536;
#pragma unroll
    for (int nt = 0; nt < 8; nt++) {
        int d = nt * 8 + (lane & 3) * 2;
        *(float2*)(dst + (size_t)rA * 64 + d) =
            make_float2(to_tf32(oacc[nt][0] * inv0), to_tf32(oacc[nt][1] * inv0));
        *(float2*)(dst + (size_t)(rA + 8) * 64 + d) =
            make_float2(to_tf32(oacc[nt][2] * inv1), to_tf32(oacc[nt][3] * inv1));
    }
}

// ---------------------------------------------------------------------------
// Kernel 7: OUT = gather(g_att) @ Wp + bp, tf32 mma, cp.async 2-stage.
// CTA tile 64x128, block 128 (warp tile 32x64).  grid (6, 128)
// ---------------------------------------------------------------------------
__global__ __launch_bounds__(128, 3) void gemm_out_mma(const float* __restrict__ bp,
                                                       float* __restrict__ out) {
    __shared__ __align__(128) float sA[2][2048];
    __shared__ __align__(128) float sB[2][4096];

    int tid = threadIdx.x;
    int warp = tid >> 5, lane = tid & 31;
    int warpM = warp >> 1, warpN = warp & 1;
    int rowBase = blockIdx.y * 64;
    int colBase = blockIdx.x * 128;
    const float* Bsrc = g_wpT + (size_t)colBase * 768;

    uint32_t aBase = smem_u32(sA), bBase = smem_u32(sB);
    int lr = lane & 7, blk = lane >> 3;
    uint32_t aOff = (uint32_t)((warpM * 32 + (blk & 1) * 8 + lr) * 128 + (blk >> 1) * 16);
    uint32_t bOff = (uint32_t)((warpN * 64 + (blk >> 1) * 8 + lr) * 128 + (blk & 1) * 16);

    float acc[2][8][4];
#pragma unroll
    for (int mt = 0; mt < 2; mt++)
#pragma unroll
        for (int nt = 0; nt < 8; nt++)
#pragma unroll
            for (int q = 0; q < 4; q++) acc[mt][nt][q] = 0.f;

    for (int it = 0; it <= 24; it++) {
        if (it >= 2) __syncthreads();
        if (it < 24) {
            int k0 = it * 32;
            int h = k0 >> 6, dbase = k0 & 63;
            uint32_t sa = aBase + (it & 1) * 8192;
            uint32_t sb = bBase + (it & 1) * 16384;
#pragma unroll
            for (int l = 0; l < 4; l++) {
                int idx = tid + l * 128;
                int row = idx >> 3, ci = idx & 7;
                int grow = rowBase + row;
                int b_ = grow >> 10, n = grow & 1023;
                CP16(sa + sw128((uint32_t)(row * 128 + ci * 16)),
                     g_att + (size_t)(b_ * 12 + h) * 65536 + n * 64 + dbase + ci * 4);
            }
#pragma unroll
            for (int l = 0; l < 8; l++) {
                int idx = tid + l * 128;
                int row = idx >> 3, ci = idx & 7;
                CP16(sb + sw128((uint32_t)(row * 128 + ci * 16)),
                     Bsrc + (size_t)row * 768 + k0 + ci * 4);
            }
            CP_COMMIT();
        }
        if (it == 0) continue;
        if (it < 24) CP_WAIT1(); else CP_WAIT0();
        __syncthreads();

        uint32_t sa = aBase + ((it - 1) & 1) * 8192;
        uint32_t sb = bBase + ((it - 1) & 1) * 16384;
#pragma unroll
        for (int ks = 0; ks < 4; ks++) {
            uint32_t af[2][4], bf[4][4];
#pragma unroll
            for (int mt = 0; mt < 2; mt++)
                LDMX4(af[mt], sa + sw128(aOff + mt * 2048 + ks * 32));
#pragma unroll
            for (int np = 0; np < 4; np++)
                LDMX4(bf[np], sb + sw128(bOff + np * 2048 + ks * 32));
#pragma unroll
            for (int mt = 0; mt < 2; mt++)
#pragma unroll
                for (int np = 0; np < 4; np++) {
                    MMA_TF32(acc[mt][np * 2],     af[mt], bf[np][0], bf[np][1]);
                    MMA_TF32(acc[mt][np * 2 + 1], af[mt], bf[np][2], bf[np][3]);
                }
        }
    }

#pragma unroll
    for (int mt = 0; mt < 2; mt++) {
        int r0g = rowBase + warpM * 32 + mt * 16 + (lane >> 2);
#pragma unroll
        for (int nt = 0; nt < 8; nt++) {
            int col = colBase + warpN * 64 + nt * 8 + 2 * (lane & 3);
            float2 bb = *(const float2*)(bp + col);
            *(float2*)(out + (size_t)r0g * 768 + col) =
                make_float2(acc[mt][nt][0] + bb.x, acc[mt][nt][1] + bb.y);
            *(float2*)(out + (size_t)(r0g + 8) * 768 + col) =
                make_float2(acc[mt][nt][2] + bb.x, acc[mt][nt][3] + bb.y);
        }
    }
}

// ---------------------------------------------------------------------------
// Launch
// ---------------------------------------------------------------------------
extern "C" void kernel_launch(void* const* d_in, const int* in_sizes, int n_in,
                              void* d_out, int out_size) {
    const float* x   = (const float*)d_in[0];
    const float* Wq  = (const float*)d_in[1];
    const float* Wk  = (const float*)d_in[2];
    const float* Wv  = (const float*)d_in[3];
    const float* Wp  = (const float*)d_in[4];
    const float* bp  = (const float*)d_in[5];
    const float* laq = (const float*)d_in[6];
    const float* lbq = (const float*)d_in[7];
    const float* lak = (const float*)d_in[8];
    const float* lbk = (const float*)d_in[9];
    const float* lav = (const float*)d_in[10];
    const float* lbv = (const float*)d_in[11];
    const float* bw  = (const float*)d_in[12];
    float* out = (float*)d_out;

    build_weffT<<<dim3(24, 24, 3), 256>>>(Wq, Wk, Wv, laq, lbq, lak, lbk, lav, lbv, bw);
    transpose_wp<<<dim3(24, 24), 256>>>(Wp);
    round_x<<<6144, 256>>>(x);
    gemm_qkv_mma<<<dim3(18, 128), 128>>>();
    transpose_v<<<dim3(32, 2, 96), 256>>>();
    flash_mma<<<dim3(16, 96), 128>>>();
    gemm_out_mma<<<dim3(6, 128), 128>>>(bp, out);
}